// round 13
// baseline (speedup 1.0000x reference)
#include <cuda_runtime.h>

#define BATCH 8
#define SEQ   2048
#define EMB   1024
#define HS    64
#define MROWS (BATCH*SEQ)

// pair-interleave permutation within an 8-group: mem order [0,4,1,5,2,6,3,7]
#define PPERM(l) (((l) < 4) ? (2 * (l)) : (2 * (l) - 7))

typedef unsigned long long u64;
typedef unsigned int u32;

// Q pre-scaled by log2(e)/32 (folded into Wq). Q,K natural rows [b][t][dperm]
// (d pair-interleaved); V transposed [b*64+h][t] with t pair-interleaved.
__device__ float g_Q [(size_t)MROWS * HS];
__device__ float g_K [(size_t)MROWS * HS];
__device__ float g_Vt[(size_t)MROWS * HS];
// Weights TRANSPOSED [n][k] (EMB per row), k pair-interleaved within 8-groups,
// tf32-rounded (Wq pre-scaled; V split into hi/lo).
__device__ float g_Wqr[HS * EMB];
__device__ float g_Wkr[HS * EMB];
__device__ float g_Wvh[HS * EMB];
__device__ float g_Wvl[HS * EMB];

__device__ const int qt_map[32] = {
    0,4,8,12,29,25,21,17,1,5,9,13,28,24,20,16,
    2,6,10,14,31,27,23,19,3,7,11,15,30,26,22,18};

__device__ __forceinline__ u64 pack2(float x, float y) {
    u64 r; asm("mov.b64 %0, {%1, %2};" : "=l"(r) : "f"(x), "f"(y)); return r;
}
__device__ __forceinline__ u32 tf32r(float x) {
    u32 r; asm("cvt.rna.tf32.f32 %0, %1;" : "=r"(r) : "f"(x)); return r;
}
__device__ __forceinline__ u32 f2u(float x) { return __float_as_uint(x); }
__device__ __forceinline__ float u2f(u32 x) { return __uint_as_float(x); }
__device__ __forceinline__ u32 lo32(u64 v) { return (u32)v; }
__device__ __forceinline__ u32 hi32(u64 v) { return (u32)(v >> 32); }
__device__ __forceinline__ float ex2(float x) {
    float y; asm("ex2.approx.f32 %0, %1;" : "=f"(y) : "f"(x)); return y;
}
__device__ __forceinline__ void mma8(float* c, u32 a0, u32 a1, u32 a2, u32 a3,
                                     u32 b0, u32 b1) {
    asm volatile(
        "mma.sync.aligned.m16n8k8.row.col.f32.tf32.tf32.f32 "
        "{%0,%1,%2,%3}, {%4,%5,%6,%7}, {%8,%9}, {%0,%1,%2,%3};"
        : "+f"(c[0]), "+f"(c[1]), "+f"(c[2]), "+f"(c[3])
        : "r"(a0), "r"(a1), "r"(a2), "r"(a3), "r"(b0), "r"(b1));
}
__device__ __forceinline__ u32 sm2u(const void* p) {
    return (u32)__cvta_generic_to_shared(p);
}
__device__ __forceinline__ void cpa16(u32 d, const void* s) {
    asm volatile("cp.async.cg.shared.global [%0], [%1], 16;" :: "r"(d), "l"(s));
}
__device__ __forceinline__ void cpa_commit() {
    asm volatile("cp.async.commit_group;");
}
template<int N> __device__ __forceinline__ void cpa_wait() {
    asm volatile("cp.async.wait_group %0;" :: "n"(N));
}

// ============================================================================
// prep_w (unchanged from r12): round / split / transpose / k-pair-permute.
// ============================================================================
__global__ void prep_w(const float* __restrict__ Wq, const float* __restrict__ Wk,
                       const float* __restrict__ Wv)
{
    __shared__ float sq[16][65], sk[16][65], svh[16][65], svl[16][65];
    const int tid = threadIdx.x;
    const int k0 = blockIdx.x * 16;
    {
        const int kk = tid >> 4, n4 = (tid & 15) * 4;
        float4 q = *(const float4*)(Wq + (size_t)(k0 + kk) * HS + n4);
        float4 k = *(const float4*)(Wk + (size_t)(k0 + kk) * HS + n4);
        float4 v = *(const float4*)(Wv + (size_t)(k0 + kk) * HS + n4);
        #pragma unroll
        for (int j = 0; j < 4; j++) {
            float qv = (&q.x)[j], kv = (&k.x)[j], vv = (&v.x)[j];
            sq[kk][n4 + j] = u2f(tf32r(qv * 0.04508422583f));  // (1/32)*log2(e)
            sk[kk][n4 + j] = u2f(tf32r(kv));
            u32 h = tf32r(vv);
            svh[kk][n4 + j] = u2f(h);
            svl[kk][n4 + j] = u2f(tf32r(vv - u2f(h)));
        }
    }
    __syncthreads();
    const int n = tid >> 2, j4 = (tid & 3) * 4;
    float4 oq, ok, oh, ol;
    #pragma unroll
    for (int i = 0; i < 4; i++) {
        int p = j4 + i;
        int w = p & 7;
        int l = (p & 8) | ((w & 1) ? ((w + 7) >> 1) : (w >> 1));   // IPERM
        (&oq.x)[i] = sq[l][n];
        (&ok.x)[i] = sk[l][n];
        (&oh.x)[i] = svh[l][n];
        (&ol.x)[i] = svl[l][n];
    }
    const size_t o = (size_t)n * EMB + k0 + j4;
    *(float4*)(g_Wqr + o) = oq;
    *(float4*)(g_Wkr + o) = ok;
    *(float4*)(g_Wvh + o) = oh;
    *(float4*)(g_Wvl + o) = ol;
}

// ============================================================================
// Projection (unchanged from r12): BK=16, 4-stage cp.async ring; W [n][kperm]
// stride 24 (LDS.64 fragments). Pair-interleaved epilogues.
// ============================================================================
template<int NB>
__device__ __forceinline__ void proj_body(
    const float* __restrict__ X, int row0, float* SM,
    float* T0, float* T1)
{
    const int NW = (NB == 8) ? 1 : 3;
    const int SS = 2560 + NW * 1536;
    float* ES = SM;

    const int tid  = threadIdx.x;
    const int wid  = tid >> 5;
    const int lane = tid & 31;
    const int grp  = lane >> 2;
    const int t4   = lane & 3;
    const int rb   = wid << 4;

    const int xr = tid >> 2;
    const int xc = (tid & 3) * 4;
    const int wn = tid >> 2;
    const int wj = (tid & 3) * 4;

    float acc[NB][4];
    #pragma unroll
    for (int nb = 0; nb < NB; nb++)
        #pragma unroll
        for (int j = 0; j < 4; j++) acc[nb][j] = 0.f;

    auto issue = [&](int st, int k0) {
        float* xs = SM + st * SS;
        #pragma unroll
        for (int j = 0; j < 2; j++) {
            int r = xr + j * 64;
            cpa16(sm2u(xs + r * 20 + xc), X + (size_t)(row0 + r) * EMB + k0 + xc);
        }
        float* ws = xs + 2560;
        if (NB == 8) {
            cpa16(sm2u(ws + wn * 24 + wj), g_Wqr + (size_t)wn * EMB + k0 + wj);
        } else {
            cpa16(sm2u(ws + wn * 24 + wj),
                  g_Wkr + (size_t)wn * EMB + k0 + wj);
            cpa16(sm2u(ws + 1536 + wn * 24 + wj),
                  g_Wvh + (size_t)wn * EMB + k0 + wj);
            cpa16(sm2u(ws + 3072 + wn * 24 + wj),
                  g_Wvl + (size_t)wn * EMB + k0 + wj);
        }
        cpa_commit();
    };
    issue(0, 0); issue(1, 16); issue(2, 32);

    for (int t = 0; t < 64; t++) {
        if (t <= 61)      cpa_wait<2>();
        else if (t == 62) cpa_wait<1>();
        else              cpa_wait<0>();
        __syncthreads();
        if (t + 3 < 64) issue((t + 3) & 3, (t + 3) * 16);

        const float* xs = SM + (t & 3) * SS;
        const float* ws = xs + 2560;
        #pragma unroll
        for (int ks = 0; ks < 2; ks++) {
            const int k0 = ks * 8;
            float a0f = xs[(rb + grp) * 20 + k0 + t4];
            float a1f = xs[(rb + grp + 8) * 20 + k0 + t4];
            float a2f = xs[(rb + grp) * 20 + k0 + t4 + 4];
            float a3f = xs[(rb + grp + 8) * 20 + k0 + t4 + 4];
            u32 ah0 = tf32r(a0f), ah1 = tf32r(a1f);
            u32 ah2 = tf32r(a2f), ah3 = tf32r(a3f);
            u32 al0 = 0, al1 = 0, al2 = 0, al3 = 0;
            if (NB == 16) {
                al0 = tf32r(a0f - u2f(ah0));
                al1 = tf32r(a1f - u2f(ah1));
                al2 = tf32r(a2f - u2f(ah2));
                al3 = tf32r(a3f - u2f(ah3));
            }
            #pragma unroll
            for (int nb = 0; nb < 8; nb++) {
                const int n = nb * 8 + grp;
                u64 wb = *(const u64*)&ws[n * 24 + k0 + 2 * t4];
                mma8(acc[nb], ah0, ah1, ah2, ah3, lo32(wb), hi32(wb));
                if (NB == 16) {
                    u64 wh = *(const u64*)&ws[1536 + n * 24 + k0 + 2 * t4];
                    u64 wl = *(const u64*)&ws[3072 + n * 24 + k0 + 2 * t4];
                    mma8(acc[8 + nb], ah0, ah1, ah2, ah3, lo32(wh), hi32(wh));
                    mma8(acc[8 + nb], al0, al1, al2, al3, lo32(wh), hi32(wh));
                    mma8(acc[8 + nb], ah0, ah1, ah2, ah3, lo32(wl), hi32(wl));
                }
            }
        }
    }

    // ---- epilogue ----
    __syncthreads();
    const int bglob = row0 >> 11;
    const int trow  = row0 & 2047;

    #pragma unroll
    for (int nb = 0; nb < 8; nb++) {
        const int cm0 = nb * 8 + PPERM(2 * t4);
        const int cm1 = nb * 8 + PPERM(2 * t4 + 1);
        ES[(rb + grp) * 68 + cm0]     = u2f(tf32r(acc[nb][0]));
        ES[(rb + grp) * 68 + cm1]     = u2f(tf32r(acc[nb][1]));
        ES[(rb + grp + 8) * 68 + cm0] = u2f(tf32r(acc[nb][2]));
        ES[(rb + grp + 8) * 68 + cm1] = u2f(tf32r(acc[nb][3]));
    }
    __syncthreads();
    #pragma unroll
    for (int i = 0; i < 8; i++) {
        int f = tid + i * 256;
        int r = f >> 4, c4 = (f & 15) * 4;
        *(float4*)(T0 + (size_t)(row0 + r) * HS + c4) =
            *(const float4*)&ES[r * 68 + c4];
    }

    if (NB == 16) {
        __syncthreads();
        const int rpm = rb + PPERM(grp);
        #pragma unroll
        for (int nb = 0; nb < 8; nb++) {
            const int h2 = nb * 8 + 2 * t4;
            ES[h2 * 132 + rpm]           = u2f(tf32r(acc[8 + nb][0]));
            ES[(h2 + 1) * 132 + rpm]     = u2f(tf32r(acc[8 + nb][1]));
            ES[h2 * 132 + rpm + 8]       = u2f(tf32r(acc[8 + nb][2]));
            ES[(h2 + 1) * 132 + rpm + 8] = u2f(tf32r(acc[8 + nb][3]));
        }
        __syncthreads();
        #pragma unroll
        for (int i = 0; i < 8; i++) {
            int f = tid + i * 256;
            int h = f >> 5, r4 = (f & 31) * 4;
            *(float4*)(T1 + (size_t)(bglob * 64 + h) * SEQ + trow + r4) =
                *(const float4*)&ES[h * 132 + r4];
        }
    }
}

#define PROJ_SMB (4 * 7168 * 4)   // 114688 B

__global__ __launch_bounds__(256, 2) void proj_kernel(
    const float* __restrict__ Xq, const float* __restrict__ Xkv)
{
    extern __shared__ float SM[];
    const int row0 = blockIdx.x * 128;
    if (blockIdx.y == 0)
        proj_body<8>(Xq, row0, SM, g_Q, (float*)0);
    else
        proj_body<16>(Xkv, row0, SM, g_K, g_Vt);
}

// ============================================================================
// Flash attention, 512 THREADS / 16 warps: QK warps 0-7 = (rowgrp, key-half),
// PV warps 8-15 = (rowgrp, h-half). 2 blocks/SM -> 32 warps/SM for latency
// hiding. l kept as two per-half partials, summed at normalization.
// ============================================================================
#define KST 72
#define PST 68
#define AKS0 0
#define AKS1 4608
#define AVS0 9216
#define AVS1 13824
#define APS0 18432
#define APS1 22784
#define ALS  27136
#define ASMF 27264    // floats = 109056 B

__global__ __launch_bounds__(512, 2) void attn_kernel(float* __restrict__ out)
{
    extern __shared__ float sm[];
    const int tid  = threadIdx.x;
    const int wid  = tid >> 5;          // 0..15
    const int lane = tid & 31;
    const int grp  = lane >> 2;
    const int t4   = lane & 3;
    const int rb   = (wid & 3) << 4;    // row-group base (both roles)
    const int r0   = rb + grp;
    const int half = (wid >> 2) & 1;    // key-half (QK) / h-half (PV)
    const int nbo  = half * 4;          // nb offset for this warp

    const int b = blockIdx.y;
    const int qt = qt_map[blockIdx.x];
    const int qrow0 = qt * 64;

    const float* Qg = g_Q  + ((size_t)b * SEQ + qrow0) * HS;
    const float* Kg = g_K  + (size_t)b * SEQ * HS;
    const float* Vg = g_Vt + (size_t)(b * 64) * SEQ;

    const int fr = tid >> 3;            // fill row 0..63
    const int fc = (tid & 7) * 4;       // fill col base (2 passes of +32)

    // prologue: async K(0); Q staged sync into KS1; grab Q fragments
    #pragma unroll
    for (int i = 0; i < 2; i++) {
        int c = fc + i * 32;
        cpa16(sm2u(sm + AKS0 + fr * KST + c), Kg + (size_t)fr * HS + c);
    }
    cpa_commit();
    #pragma unroll
    for (int i = 0; i < 2; i++) {
        int c = fc + i * 32;
        *(float4*)&sm[AKS1 + fr * KST + c] = *(const float4*)(Qg + (size_t)fr * HS + c);
    }
    cpa_wait<0>();
    __syncthreads();

    u32 aq[8][4];
    if (wid < 8) {
        #pragma unroll
        for (int kk = 0; kk < 8; kk++) {
            const int d0 = kk * 8;
            u64 qa = *(const u64*)&sm[AKS1 + r0 * KST + d0 + 2 * t4];
            u64 qb = *(const u64*)&sm[AKS1 + (r0 + 8) * KST + d0 + 2 * t4];
            aq[kk][0] = lo32(qa);
            aq[kk][1] = lo32(qb);
            aq[kk][2] = hi32(qa);
            aq[kk][3] = hi32(qb);
        }
    }

    float acc[4][4];                    // PV: 16 rows x 32 h-cols
    #pragma unroll
    for (int nb = 0; nb < 4; nb++)
        #pragma unroll
        for (int j = 0; j < 4; j++) acc[nb][j] = 0.f;
    float l0 = 0.f, l1 = 0.f;           // QK partial row sums (this key-half)

    const int pc0 = PPERM(2 * t4);
    const int pc1 = PPERM(2 * t4 + 1);

    for (int kt = 0; kt <= qt; kt++) {
        cpa_wait<0>();            // K(kt), V(kt-1) landed
        __syncthreads();          // visible; P(kt-1) visible
        const int p = kt & 1;

        if (kt < qt) {
            float* ksn = sm + (p ? AKS0 : AKS1);
            #pragma unroll
            for (int i = 0; i < 2; i++) {
                int c = fc + i * 32;
                cpa16(sm2u(ksn + fr * KST + c),
                      Kg + (size_t)((kt + 1) * 64 + fr) * HS + c);
            }
        }
        {
            float* vsn = sm + (p ? AVS1 : AVS0);
            #pragma unroll
            for (int i = 0; i < 2; i++) {
                int c = fc + i * 32;
                cpa16(sm2u(vsn + fr * KST + c),
                      Vg + (size_t)fr * SEQ + kt * 64 + c);
            }
        }
        cpa_commit();

        if (wid < 8) {
            // ---- QK(kt) on this key-half + exp2 ----
            const float* KSp = sm + (p ? AKS1 : AKS0);
            float S[4][4];
            #pragma unroll
            for (int nb = 0; nb < 4; nb++)
                #pragma unroll
                for (int j = 0; j < 4; j++) S[nb][j] = 0.f;
            #pragma unroll
            for (int kk = 0; kk < 8; kk++) {
                const int d0 = kk * 8;
                #pragma unroll
                for (int nb = 0; nb < 4; nb++) {
                    u64 bb = *(const u64*)
                        &KSp[((nbo + nb) * 8 + grp) * KST + d0 + 2 * t4];
                    mma8(S[nb], aq[kk][0], aq[kk][1], aq[kk][2], aq[kk][3],
                         lo32(bb), hi32(bb));
                }
            }
            if (kt == qt) {   // causal mask on diagonal tile
                #pragma unroll
                for (int nb = 0; nb < 4; nb++) {
                    int c0 = (nbo + nb) * 8 + 2 * t4;
                    if (c0     > r0)     S[nb][0] = -1e30f;
                    if (c0 + 1 > r0)     S[nb][1] = -1e30f;
                    if (c0     > r0 + 8) S[nb][2] = -1e30f;
                    if (c0 + 1 > r0 + 8) S[nb][3] = -1e30f;
                }
            }
            float* PSb = sm + (p ? APS1 : APS0);
            #pragma unroll
            for (int nb = 0; nb < 4; nb++) {
                u32 p0 = tf32r(ex2(S[nb][0]));
                u32 p1 = tf32r(ex2(S[nb][1]));
                u32 p2 = tf32r(ex2(S[nb][2]));
                u32 p3 = tf32r(ex2(S[nb][3]));
                l0 += u2f(p0) + u2f(p1);
                l1 += u2f(p2) + u2f(p3);
                PSb[r0 * PST + (nbo + nb) * 8 + pc0]       = u2f(p0);
                PSb[r0 * PST + (nbo + nb) * 8 + pc1]       = u2f(p1);
                PSb[(r0 + 8) * PST + (nbo + nb) * 8 + pc0] = u2f(p2);
                PSb[(r0 + 8) * PST + (nbo + nb) * 8 + pc1] = u2f(p3);
            }
        } else if (kt > 0) {
            // ---- PV(kt-1) on this h-half ----
            const int q2 = p ^ 1;
            const float* PSb = sm + (q2 ? APS1 : APS0);
            const float* VSp = sm + (q2 ? AVS1 : AVS0);
            #pragma unroll
            for (int ks = 0; ks < 8; ks++) {
                const int k0 = ks * 8;
                u64 pa = *(const u64*)&PSb[r0 * PST + k0 + 2 * t4];
                u64 pb = *(const u64*)&PSb[(r0 + 8) * PST + k0 + 2 * t4];
                u32 a0 = lo32(pa), a1 = lo32(pb), a2 = hi32(pa), a3 = hi32(pb);
                #pragma unroll
                for (int nb = 0; nb < 4; nb++) {
                    u64 vv = *(const u64*)
                        &VSp[((nbo + nb) * 8 + grp) * KST + k0 + 2 * t4];
                    mma8(acc[nb], a0, a1, a2, a3, lo32(vv), hi32(vv));
                }
            }
        }
    }

    // drain: publish l partials, final PV(qt), normalize, store
    cpa_wait<0>();        // V(qt) landed
    __syncthreads();      // P(qt) visible
    if (wid < 8) {
        l0 += __shfl_xor_sync(0xffffffffu, l0, 1);
        l0 += __shfl_xor_sync(0xffffffffu, l0, 2);
        l1 += __shfl_xor_sync(0xffffffffu, l1, 1);
        l1 += __shfl_xor_sync(0xffffffffu, l1, 2);
        if (t4 == 0) {
            sm[ALS + half * 64 + r0]     = l0;
            sm[ALS + half * 64 + r0 + 8] = l1;
        }
    } else {
        const int q2 = qt & 1;
        const float* PSb = sm + (q2 ? APS1 : APS0);
        const float* VSp = sm + (q2 ? AVS1 : AVS0);
        #pragma unroll
        for (int ks = 0; ks < 8; ks++) {
            const int k0 = ks * 8;
            u64 pa = *(const u64*)&PSb[r0 * PST + k0 + 2 * t4];
            u64 pb = *(const u64*)&PSb[(r0 + 8) * PST + k0 + 2 * t4];
            u32 a0 = lo32(pa), a1 = lo32(pb), a2 = hi32(pa), a3 = hi32(pb);
            #pragma unroll
            for (int nb = 0; nb < 4; nb++) {
                u64 vv = *(const u64*)
                    &VSp[((nbo + nb) * 8 + grp) * KST + k0 + 2 * t4];
                mma8(acc[nb], a0, a1, a2, a3, lo32(vv), hi32(vv));
            }
        }
    }
    __syncthreads();
    if (wid >= 8) {
        const float inv0 = 1.0f / (sm[ALS + r0]     + sm[ALS + 64 + r0]);
        const float inv1 = 1.0f / (sm[ALS + r0 + 8] + sm[ALS + 64 + r0 + 8]);
        float* o0 = out + ((size_t)b * SEQ + qrow0 + r0) * HS;
        float* o8 = o0 + 8 * HS;
        #pragma unroll
        for (int nb = 0; nb < 4; nb++) {
            *(u64*)(o0 + (nbo + nb) * 8 + 2 * t4) =
                pack2(acc[nb][0] * inv0, acc[nb][1] * inv0);
            *(u64*)(o8 + (nbo + nb) * 8 + 2 * t4) =
                pack2(acc[nb][2] * inv1, acc[nb][3] * inv1);
        }
    }
}

extern "C" void kernel_launch(void* const* d_in, const int* in_sizes, int n_in,
                              void* d_out, int out_size)
{
    (void)in_sizes; (void)n_in; (void)out_size;
    const float* index  = (const float*)d_in[0];
    const float* memory = (const float*)d_in[1];
    const float* Wq     = (const float*)d_in[2];
    const float* Wk     = (const float*)d_in[3];
    const float* Wv     = (const float*)d_in[4];
    float* out = (float*)d_out;

    cudaFuncSetAttribute(proj_kernel,
                         cudaFuncAttributeMaxDynamicSharedMemorySize, PROJ_SMB);
    cudaFuncSetAttribute(attn_kernel,
                         cudaFuncAttributeMaxDynamicSharedMemorySize, ASMF * 4);

    prep_w<<<64, 256>>>(Wq, Wk, Wv);
    proj_kernel<<<dim3(128, 2), 256, PROJ_SMB>>>(index, memory);
    attn_kernel<<<dim3(32, 8), 512, ASMF * 4>>>(out);
}

// round 14
// speedup vs baseline: 1.2951x; 1.2951x over previous
#include <cuda_runtime.h>

#define BATCH 8
#define SEQ   2048
#define EMB   1024
#define HS    64
#define MROWS (BATCH*SEQ)

// pair-interleave permutation within an 8-group: mem order [0,4,1,5,2,6,3,7]
#define PPERM(l) (((l) < 4) ? (2 * (l)) : (2 * (l) - 7))

typedef unsigned long long u64;
typedef unsigned int u32;

// Q pre-scaled by 1/32. Q,K natural rows [b][t][dperm] (d pair-interleaved);
// V transposed [b*64+h][t] with t pair-interleaved within each 8-group. tf32-exact.
__device__ float g_Q [(size_t)MROWS * HS];
__device__ float g_K [(size_t)MROWS * HS];
__device__ float g_Vt[(size_t)MROWS * HS];
// Pre-rounded weights, [k][n] row-major (n contiguous, 64 wide).
// V keeps only the hi part (2-term split: x_hi@w_hi + x_lo@w_hi).
__device__ float g_Wqr[EMB * HS];
__device__ float g_Wkr[EMB * HS];
__device__ float g_Wvh[EMB * HS];

__device__ const int qt_map[32] = {
    0,4,8,12,29,25,21,17,1,5,9,13,28,24,20,16,
    2,6,10,14,31,27,23,19,3,7,11,15,30,26,22,18};

__device__ __forceinline__ u64 pack2(float x, float y) {
    u64 r; asm("mov.b64 %0, {%1, %2};" : "=l"(r) : "f"(x), "f"(y)); return r;
}
__device__ __forceinline__ u32 tf32r(float x) {
    u32 r; asm("cvt.rna.tf32.f32 %0, %1;" : "=r"(r) : "f"(x)); return r;
}
__device__ __forceinline__ u32 f2u(float x) { return __float_as_uint(x); }
__device__ __forceinline__ float u2f(u32 x) { return __uint_as_float(x); }
__device__ __forceinline__ u32 lo32(u64 v) { return (u32)v; }
__device__ __forceinline__ u32 hi32(u64 v) { return (u32)(v >> 32); }
__device__ __forceinline__ void mma8(float* c, u32 a0, u32 a1, u32 a2, u32 a3,
                                     u32 b0, u32 b1) {
    asm volatile(
        "mma.sync.aligned.m16n8k8.row.col.f32.tf32.tf32.f32 "
        "{%0,%1,%2,%3}, {%4,%5,%6,%7}, {%8,%9}, {%0,%1,%2,%3};"
        : "+f"(c[0]), "+f"(c[1]), "+f"(c[2]), "+f"(c[3])
        : "r"(a0), "r"(a1), "r"(a2), "r"(a3), "r"(b0), "r"(b1));
}
__device__ __forceinline__ u32 sm2u(const void* p) {
    return (u32)__cvta_generic_to_shared(p);
}
__device__ __forceinline__ void cpa16(u32 d, const void* s) {
    asm volatile("cp.async.cg.shared.global [%0], [%1], 16;" :: "r"(d), "l"(s));
}
__device__ __forceinline__ void cpa_commit() {
    asm volatile("cp.async.commit_group;");
}
template<int N> __device__ __forceinline__ void cpa_wait() {
    asm volatile("cp.async.wait_group %0;" :: "n"(N));
}

// ============================================================================
// prep_w: round weights once (V hi-part only; 2-term split).
// ============================================================================
__global__ void prep_w(const float* __restrict__ Wq, const float* __restrict__ Wk,
                       const float* __restrict__ Wv)
{
    int i = blockIdx.x * 256 + threadIdx.x;     // 65536 elements
    g_Wqr[i] = u2f(tf32r(Wq[i]));
    g_Wkr[i] = u2f(tf32r(Wk[i]));
    g_Wvh[i] = u2f(tf32r(Wv[i]));
}

// ============================================================================
// Projection (round-11 config): BK=16, 4-stage cp.async ring, precise tail
// waits. X [r][k] s20; W regions [k][n] s72 (raw async copies of pre-rounded
// W). NB=8: Q (pre-scaled 1/32) -> natural rows. NB=16: K -> natural rows,
// V (2-term split: ah@wh + al@wh) -> transposed. Pair-interleaved epilogues.
// ============================================================================
template<int NB>
__device__ __forceinline__ void proj_body(
    const float* __restrict__ X, int row0, float* SM,
    float* T0, float* T1)
{
    const int NW  = (NB == 8) ? 1 : 2;
    const int SS  = 2560 + NW * 1152;
    float* ES = SM;

    const int tid  = threadIdx.x;
    const int wid  = tid >> 5;
    const int lane = tid & 31;
    const int grp  = lane >> 2;
    const int t4   = lane & 3;
    const int rb   = wid << 4;

    const int xr = tid >> 2;
    const int xc = (tid & 3) * 4;
    const int wk = tid >> 4;
    const int wn = (tid & 15) * 4;

    float acc[NB][4];
    #pragma unroll
    for (int nb = 0; nb < NB; nb++)
        #pragma unroll
        for (int j = 0; j < 4; j++) acc[nb][j] = 0.f;

    auto issue = [&](int st, int k0) {
        float* xs = SM + st * SS;
        #pragma unroll
        for (int j = 0; j < 2; j++) {
            int r = xr + j * 64;
            cpa16(sm2u(xs + r * 20 + xc), X + (size_t)(row0 + r) * EMB + k0 + xc);
        }
        float* ws = xs + 2560;
        if (NB == 8) {
            cpa16(sm2u(ws + wk * 72 + wn), g_Wqr + (size_t)(k0 + wk) * HS + wn);
        } else {
            cpa16(sm2u(ws + wk * 72 + wn),
                  g_Wkr + (size_t)(k0 + wk) * HS + wn);
            cpa16(sm2u(ws + 1152 + wk * 72 + wn),
                  g_Wvh + (size_t)(k0 + wk) * HS + wn);
        }
        cpa_commit();
    };
    issue(0, 0); issue(1, 16); issue(2, 32);

    for (int t = 0; t < 64; t++) {
        if (t <= 61)      cpa_wait<2>();
        else if (t == 62) cpa_wait<1>();
        else              cpa_wait<0>();
        __syncthreads();
        if (t + 3 < 64) issue((t + 3) & 3, (t + 3) * 16);

        const float* xs = SM + (t & 3) * SS;
        const float* ws = xs + 2560;
        #pragma unroll
        for (int ks = 0; ks < 2; ks++) {
            const int k0 = ks * 8;
            float a0f = xs[(rb + grp) * 20 + k0 + t4];
            float a1f = xs[(rb + grp + 8) * 20 + k0 + t4];
            float a2f = xs[(rb + grp) * 20 + k0 + t4 + 4];
            float a3f = xs[(rb + grp + 8) * 20 + k0 + t4 + 4];
            u32 ah0 = tf32r(a0f), ah1 = tf32r(a1f);
            u32 ah2 = tf32r(a2f), ah3 = tf32r(a3f);
            u32 al0 = 0, al1 = 0, al2 = 0, al3 = 0;
            if (NB == 16) {
                al0 = tf32r(a0f - u2f(ah0));
                al1 = tf32r(a1f - u2f(ah1));
                al2 = tf32r(a2f - u2f(ah2));
                al3 = tf32r(a3f - u2f(ah3));
            }
            #pragma unroll
            for (int nb = 0; nb < 8; nb++) {
                const int n = nb * 8 + grp;
                u32 b0 = f2u(ws[(k0 + t4) * 72 + n]);
                u32 b1 = f2u(ws[(k0 + t4 + 4) * 72 + n]);
                mma8(acc[nb], ah0, ah1, ah2, ah3, b0, b1);
                if (NB == 16) {
                    u32 bh0 = f2u(ws[1152 + (k0 + t4) * 72 + n]);
                    u32 bh1 = f2u(ws[1152 + (k0 + t4 + 4) * 72 + n]);
                    mma8(acc[8 + nb], ah0, ah1, ah2, ah3, bh0, bh1);
                    mma8(acc[8 + nb], al0, al1, al2, al3, bh0, bh1);
                }
            }
        }
    }

    // ---- epilogue (ring drained: wait<0> ran at t=63) ----
    __syncthreads();
    const int bglob = row0 >> 11;
    const int trow  = row0 & 2047;
    const float qs = (NB == 8) ? 0.03125f : 1.0f;   // fold 1/sqrt(1024) into Q

    // Q/K: d-permuted columns (pair interleave)
    #pragma unroll
    for (int nb = 0; nb < 8; nb++) {
        const int cm0 = nb * 8 + PPERM(2 * t4);
        const int cm1 = nb * 8 + PPERM(2 * t4 + 1);
        ES[(rb + grp) * 68 + cm0]     = u2f(tf32r(acc[nb][0] * qs));
        ES[(rb + grp) * 68 + cm1]     = u2f(tf32r(acc[nb][1] * qs));
        ES[(rb + grp + 8) * 68 + cm0] = u2f(tf32r(acc[nb][2] * qs));
        ES[(rb + grp + 8) * 68 + cm1] = u2f(tf32r(acc[nb][3] * qs));
    }
    __syncthreads();
    #pragma unroll
    for (int i = 0; i < 8; i++) {
        int f = tid + i * 256;
        int r = f >> 4, c4 = (f & 15) * 4;
        *(float4*)(T0 + (size_t)(row0 + r) * HS + c4) =
            *(const float4*)&ES[r * 68 + c4];
    }

    if (NB == 16) {   // V transposed via ES [h][r] s132; key-rows pair-interleaved
        __syncthreads();
        const int rpm = rb + PPERM(grp);
        #pragma unroll
        for (int nb = 0; nb < 8; nb++) {
            const int h2 = nb * 8 + 2 * t4;
            ES[h2 * 132 + rpm]           = u2f(tf32r(acc[8 + nb][0]));
            ES[(h2 + 1) * 132 + rpm]     = u2f(tf32r(acc[8 + nb][1]));
            ES[h2 * 132 + rpm + 8]       = u2f(tf32r(acc[8 + nb][2]));
            ES[(h2 + 1) * 132 + rpm + 8] = u2f(tf32r(acc[8 + nb][3]));
        }
        __syncthreads();
        #pragma unroll
        for (int i = 0; i < 8; i++) {
            int f = tid + i * 256;
            int h = f >> 5, r4 = (f & 31) * 4;
            *(float4*)(T1 + (size_t)(bglob * 64 + h) * SEQ + trow + r4) =
                *(const float4*)&ES[h * 132 + r4];
        }
    }
}

#define PROJ_SMB (4 * (2560 + 2 * 1152) * 4)   // 77824 B

__global__ __launch_bounds__(256, 2) void proj_kernel(
    const float* __restrict__ Xq, const float* __restrict__ Xkv)
{
    extern __shared__ float SM[];
    const int row0 = blockIdx.x * 128;
    if (blockIdx.y == 0)
        proj_body<8>(Xq, row0, SM, g_Q, (float*)0);
    else
        proj_body<16>(Xkv, row0, SM, g_K, g_Vt);
}

// ============================================================================
// Flash attention (byte-identical to round 11, the 202.1us best):
// warps 0-3 QK(kt)+exp (no max subtraction; logits bounded), warps 4-7
// PV(kt-1). Pair-interleaved layouts -> all mma fragment loads are LDS.64:
// K [key][dperm] s72; V [h][keyperm] s72; P [r][keyperm] s68.
// ============================================================================
#define KST 72
#define PST 68
#define AKS0 0
#define AKS1 4608
#define AVS0 9216
#define AVS1 13824
#define APS0 18432
#define APS1 22784
#define ALS  27136
#define ASMF 27200    // floats = 108800 B

__global__ __launch_bounds__(256, 2) void attn_kernel(float* __restrict__ out)
{
    extern __shared__ float sm[];
    const int tid  = threadIdx.x;
    const int wid  = tid >> 5;
    const int lane = tid & 31;
    const int grp  = lane >> 2;
    const int t4   = lane & 3;
    const int rb   = (wid & 3) << 4;
    const int r0   = rb + grp;

    const int b = blockIdx.y;
    const int qt = qt_map[blockIdx.x];
    const int qrow0 = qt * 64;

    const float* Qg = g_Q  + ((size_t)b * SEQ + qrow0) * HS;
    const float* Kg = g_K  + (size_t)b * SEQ * HS;
    const float* Vg = g_Vt + (size_t)(b * 64) * SEQ;

    const int fr  = tid >> 2;
    const int fcb = (tid & 3) * 4;

    // prologue: async K(0); Q staged sync into KS1; grab Q fragments
    #pragma unroll
    for (int i = 0; i < 4; i++) {
        int c = fcb + i * 16;
        cpa16(sm2u(sm + AKS0 + fr * KST + c), Kg + (size_t)fr * HS + c);
    }
    cpa_commit();
    #pragma unroll
    for (int i = 0; i < 4; i++) {
        int c = fcb + i * 16;
        *(float4*)&sm[AKS1 + fr * KST + c] = *(const float4*)(Qg + (size_t)fr * HS + c);
    }
    cpa_wait<0>();
    __syncthreads();

    u32 aq[8][4];
    if (wid < 4) {
        #pragma unroll
        for (int kk = 0; kk < 8; kk++) {
            const int d0 = kk * 8;
            u64 qa = *(const u64*)&sm[AKS1 + r0 * KST + d0 + 2 * t4];
            u64 qb = *(const u64*)&sm[AKS1 + (r0 + 8) * KST + d0 + 2 * t4];
            aq[kk][0] = lo32(qa);
            aq[kk][1] = lo32(qb);
            aq[kk][2] = hi32(qa);
            aq[kk][3] = hi32(qb);
        }
    }

    float acc[8][4];
    #pragma unroll
    for (int nb = 0; nb < 8; nb++)
        #pragma unroll
        for (int j = 0; j < 4; j++) acc[nb][j] = 0.f;
    float l0 = 0.f, l1 = 0.f;

    const int pc0 = PPERM(2 * t4);
    const int pc1 = PPERM(2 * t4 + 1);

    for (int kt = 0; kt <= qt; kt++) {
        cpa_wait<0>();
        __syncthreads();
        const int p = kt & 1;

        if (kt < qt) {
            float* ksn = sm + (p ? AKS0 : AKS1);
            #pragma unroll
            for (int i = 0; i < 4; i++) {
                int c = fcb + i * 16;
                cpa16(sm2u(ksn + fr * KST + c),
                      Kg + (size_t)((kt + 1) * 64 + fr) * HS + c);
            }
        }
        {
            float* vsn = sm + (p ? AVS1 : AVS0);
            #pragma unroll
            for (int i = 0; i < 4; i++) {
                int c = fcb + i * 16;
                cpa16(sm2u(vsn + fr * KST + c),
                      Vg + (size_t)fr * SEQ + kt * 64 + c);
            }
        }
        cpa_commit();

        if (wid < 4) {
            const float* KSp = sm + (p ? AKS1 : AKS0);
            float S[8][4];
            #pragma unroll
            for (int nb = 0; nb < 8; nb++)
                #pragma unroll
                for (int j = 0; j < 4; j++) S[nb][j] = 0.f;
            #pragma unroll
            for (int kk = 0; kk < 8; kk++) {
                const int d0 = kk * 8;
                #pragma unroll
                for (int nb = 0; nb < 8; nb++) {
                    u64 bb = *(const u64*)&KSp[(nb * 8 + grp) * KST + d0 + 2 * t4];
                    mma8(S[nb], aq[kk][0], aq[kk][1], aq[kk][2], aq[kk][3],
                         lo32(bb), hi32(bb));
                }
            }
            if (kt == qt) {
                #pragma unroll
                for (int nb = 0; nb < 8; nb++) {
                    int c0 = nb * 8 + 2 * t4;
                    if (c0     > r0)     S[nb][0] = -1e30f;
                    if (c0 + 1 > r0)     S[nb][1] = -1e30f;
                    if (c0     > r0 + 8) S[nb][2] = -1e30f;
                    if (c0 + 1 > r0 + 8) S[nb][3] = -1e30f;
                }
            }
            float* PSb = sm + (p ? APS1 : APS0);
            #pragma unroll
            for (int nb = 0; nb < 8; nb++) {
                u32 p0 = tf32r(__expf(S[nb][0]));
                u32 p1 = tf32r(__expf(S[nb][1]));
                u32 p2 = tf32r(__expf(S[nb][2]));
                u32 p3 = tf32r(__expf(S[nb][3]));
                l0 += u2f(p0) + u2f(p1);
                l1 += u2f(p2) + u2f(p3);
                PSb[r0 * PST + nb * 8 + pc0]       = u2f(p0);
                PSb[r0 * PST + nb * 8 + pc1]       = u2f(p1);
                PSb[(r0 + 8) * PST + nb * 8 + pc0] = u2f(p2);
                PSb[(r0 + 8) * PST + nb * 8 + pc1] = u2f(p3);
            }
        } else if (kt > 0) {
            const int q2 = p ^ 1;
            const float* PSb = sm + (q2 ? APS1 : APS0);
            const float* VSp = sm + (q2 ? AVS1 : AVS0);
            #pragma unroll
            for (int ks = 0; ks < 8; ks++) {
                const int k0 = ks * 8;
                u64 pa = *(const u64*)&PSb[r0 * PST + k0 + 2 * t4];
                u64 pb = *(const u64*)&PSb[(r0 + 8) * PST + k0 + 2 * t4];
                u32 a0 = lo32(pa), a1 = lo32(pb), a2 = hi32(pa), a3 = hi32(pb);
                #pragma unroll
                for (int nb = 0; nb < 8; nb++) {
                    u64 vv = *(const u64*)&VSp[(nb * 8 + grp) * KST + k0 + 2 * t4];
                    mma8(acc[nb], a0, a1, a2, a3, lo32(vv), hi32(vv));
                }
            }
        }
    }

    // drain: publish l, final PV(qt), normalize, store
    cpa_wait<0>();
    __syncthreads();
    if (wid < 4) {
        l0 += __shfl_xor_sync(0xffffffffu, l0, 1);
        l0 += __shfl_xor_sync(0xffffffffu, l0, 2);
        l1 += __shfl_xor_sync(0xffffffffu, l1, 1);
        l1 += __shfl_xor_sync(0xffffffffu, l1, 2);
        if (t4 == 0) {
            sm[ALS + r0]     = l0;
            sm[ALS + r0 + 8] = l1;
        }
    } else {
        const int q2 = qt & 1;
        const float* PSb = sm + (q2 ? APS1 : APS0);
        const float* VSp = sm + (q2 ? AVS1 : AVS0);
        #pragma unroll
        for (int ks = 0; ks < 8; ks++) {
            const int k0 = ks * 8;
            u64 pa = *(const u64*)&PSb[r0 * PST + k0 + 2 * t4];
            u64 pb = *(const u64*)&PSb[(r0 + 8) * PST + k0 + 2 * t4];
            u32 a0 = lo32(pa), a1 = lo32(pb), a2 = hi32(pa), a3 = hi32(pb);
            #pragma unroll
            for (int nb = 0; nb < 8; nb++) {
                u64 vv = *(const u64*)&VSp[(nb * 8 + grp) * KST + k0 + 2 * t4];
                mma8(acc[nb], a0, a1, a2, a3, lo32(vv), hi32(vv));
            }
        }
    }
    __syncthreads();
    if (wid >= 4) {
        const float inv0 = 1.0f / sm[ALS + r0];
        const float inv1 = 1.0f / sm[ALS + r0 + 8];
        float* o0 = out + ((size_t)b * SEQ + qrow0 + r0) * HS;
        float* o8 = o0 + 8 * HS;
        #pragma unroll
        for (int nb = 0; nb < 8; nb++) {
            *(u64*)(o0 + nb * 8 + 2 * t4) =
                pack2(acc[nb][0] * inv0, acc[nb][1] * inv0);
            *(u64*)(o8 + nb * 8 + 2 * t4) =
                pack2(acc[nb][2] * inv1, acc[nb][3] * inv1);
        }
    }
}

extern "C" void kernel_launch(void* const* d_in, const int* in_sizes, int n_in,
                              void* d_out, int out_size)
{
    (void)in_sizes; (void)n_in; (void)out_size;
    const float* index  = (const float*)d_in[0];
    const float* memory = (const float*)d_in[1];
    const float* Wq     = (const float*)d_in[2];
    const float* Wk     = (const float*)d_in[3];
    const float* Wv     = (const float*)d_in[4];
    float* out = (float*)d_out;

    cudaFuncSetAttribute(proj_kernel,
                         cudaFuncAttributeMaxDynamicSharedMemorySize, PROJ_SMB);
    cudaFuncSetAttribute(attn_kernel,
                         cudaFuncAttributeMaxDynamicSharedMemorySize, ASMF * 4);

    prep_w<<<256, 256>>>(Wq, Wk, Wv);
    proj_kernel<<<dim3(128, 2), 256, PROJ_SMB>>>(index, memory);
    attn_kernel<<<dim3(32, 8), 256, ASMF * 4>>>(out);
}

// round 15
// speedup vs baseline: 1.4175x; 1.0945x over previous
#include <cuda_runtime.h>

#define BATCH 8
#define SEQ   2048
#define EMB   1024
#define HS    64
#define MROWS (BATCH*SEQ)

// pair-interleave permutation within an 8-group: mem order [0,4,1,5,2,6,3,7]
#define PPERM(l) (((l) < 4) ? (2 * (l)) : (2 * (l) - 7))

typedef unsigned long long u64;
typedef unsigned int u32;

// Q pre-scaled by 1/32. Q,K natural rows [b][t][dperm] (d pair-interleaved);
// V transposed [b*64+h][t] with t pair-interleaved within each 8-group. tf32-exact.
__device__ float g_Q [(size_t)MROWS * HS];
__device__ float g_K [(size_t)MROWS * HS];
__device__ float g_Vt[(size_t)MROWS * HS];
// Pre-rounded weights, [k][n] row-major (n contiguous, 64 wide). V single-term.
__device__ float g_Wqr[EMB * HS];
__device__ float g_Wkr[EMB * HS];
__device__ float g_Wvh[EMB * HS];

__device__ const int qt_map[32] = {
    0,4,8,12,29,25,21,17,1,5,9,13,28,24,20,16,
    2,6,10,14,31,27,23,19,3,7,11,15,30,26,22,18};

__device__ __forceinline__ u64 pack2(float x, float y) {
    u64 r; asm("mov.b64 %0, {%1, %2};" : "=l"(r) : "f"(x), "f"(y)); return r;
}
__device__ __forceinline__ u32 tf32r(float x) {
    u32 r; asm("cvt.rna.tf32.f32 %0, %1;" : "=r"(r) : "f"(x)); return r;
}
__device__ __forceinline__ u32 f2u(float x) { return __float_as_uint(x); }
__device__ __forceinline__ float u2f(u32 x) { return __uint_as_float(x); }
__device__ __forceinline__ u32 lo32(u64 v) { return (u32)v; }
__device__ __forceinline__ u32 hi32(u64 v) { return (u32)(v >> 32); }
__device__ __forceinline__ void mma8(float* c, u32 a0, u32 a1, u32 a2, u32 a3,
                                     u32 b0, u32 b1) {
    asm volatile(
        "mma.sync.aligned.m16n8k8.row.col.f32.tf32.tf32.f32 "
        "{%0,%1,%2,%3}, {%4,%5,%6,%7}, {%8,%9}, {%0,%1,%2,%3};"
        : "+f"(c[0]), "+f"(c[1]), "+f"(c[2]), "+f"(c[3])
        : "r"(a0), "r"(a1), "r"(a2), "r"(a3), "r"(b0), "r"(b1));
}
__device__ __forceinline__ u32 sm2u(const void* p) {
    return (u32)__cvta_generic_to_shared(p);
}
__device__ __forceinline__ void cpa16(u32 d, const void* s) {
    asm volatile("cp.async.cg.shared.global [%0], [%1], 16;" :: "r"(d), "l"(s));
}
__device__ __forceinline__ void cpa_commit() {
    asm volatile("cp.async.commit_group;");
}
template<int N> __device__ __forceinline__ void cpa_wait() {
    asm volatile("cp.async.wait_group %0;" :: "n"(N));
}

// ============================================================================
// prep_w: round weights once.
// ============================================================================
__global__ void prep_w(const float* __restrict__ Wq, const float* __restrict__ Wk,
                       const float* __restrict__ Wv)
{
    int i = blockIdx.x * 256 + threadIdx.x;     // 65536 elements
    g_Wqr[i] = u2f(tf32r(Wq[i]));
    g_Wkr[i] = u2f(tf32r(Wk[i]));
    g_Wvh[i] = u2f(tf32r(Wv[i]));
}

// ============================================================================
// Projection: BK=16, 4-stage cp.async ring, precise tail waits.
// X [r][k] s20; W regions [k][n] s72 (raw async copies of pre-rounded W).
// NB=8: Q (pre-scaled 1/32) -> natural rows. NB=16: K -> natural rows,
// V SINGLE tf32 mma -> transposed. Pair-interleaved epilogues.
// ============================================================================
template<int NB>
__device__ __forceinline__ void proj_body(
    const float* __restrict__ X, int row0, float* SM,
    float* T0, float* T1)
{
    const int NW  = (NB == 8) ? 1 : 2;
    const int SS  = 2560 + NW * 1152;
    float* ES = SM;

    const int tid  = threadIdx.x;
    const int wid  = tid >> 5;
    const int lane = tid & 31;
    const int grp  = lane >> 2;
    const int t4   = lane & 3;
    const int rb   = wid << 4;

    const int xr = tid >> 2;
    const int xc = (tid & 3) * 4;
    const int wk = tid >> 4;
    const int wn = (tid & 15) * 4;

    float acc[NB][4];
    #pragma unroll
    for (int nb = 0; nb < NB; nb++)
        #pragma unroll
        for (int j = 0; j < 4; j++) acc[nb][j] = 0.f;

    auto issue = [&](int st, int k0) {
        float* xs = SM + st * SS;
        #pragma unroll
        for (int j = 0; j < 2; j++) {
            int r = xr + j * 64;
            cpa16(sm2u(xs + r * 20 + xc), X + (size_t)(row0 + r) * EMB + k0 + xc);
        }
        float* ws = xs + 2560;
        if (NB == 8) {
            cpa16(sm2u(ws + wk * 72 + wn), g_Wqr + (size_t)(k0 + wk) * HS + wn);
        } else {
            cpa16(sm2u(ws + wk * 72 + wn),
                  g_Wkr + (size_t)(k0 + wk) * HS + wn);
            cpa16(sm2u(ws + 1152 + wk * 72 + wn),
                  g_Wvh + (size_t)(k0 + wk) * HS + wn);
        }
        cpa_commit();
    };
    issue(0, 0); issue(1, 16); issue(2, 32);

    for (int t = 0; t < 64; t++) {
        if (t <= 61)      cpa_wait<2>();
        else if (t == 62) cpa_wait<1>();
        else              cpa_wait<0>();
        __syncthreads();
        if (t + 3 < 64) issue((t + 3) & 3, (t + 3) * 16);

        const float* xs = SM + (t & 3) * SS;
        const float* ws = xs + 2560;
        #pragma unroll
        for (int ks = 0; ks < 2; ks++) {
            const int k0 = ks * 8;
            u32 ah0 = tf32r(xs[(rb + grp) * 20 + k0 + t4]);
            u32 ah1 = tf32r(xs[(rb + grp + 8) * 20 + k0 + t4]);
            u32 ah2 = tf32r(xs[(rb + grp) * 20 + k0 + t4 + 4]);
            u32 ah3 = tf32r(xs[(rb + grp + 8) * 20 + k0 + t4 + 4]);
            #pragma unroll
            for (int nb = 0; nb < 8; nb++) {
                const int n = nb * 8 + grp;
                u32 b0 = f2u(ws[(k0 + t4) * 72 + n]);
                u32 b1 = f2u(ws[(k0 + t4 + 4) * 72 + n]);
                mma8(acc[nb], ah0, ah1, ah2, ah3, b0, b1);
                if (NB == 16) {
                    u32 bh0 = f2u(ws[1152 + (k0 + t4) * 72 + n]);
                    u32 bh1 = f2u(ws[1152 + (k0 + t4 + 4) * 72 + n]);
                    mma8(acc[8 + nb], ah0, ah1, ah2, ah3, bh0, bh1);
                }
            }
        }
    }

    // ---- epilogue (ring drained: wait<0> ran at t=63) ----
    __syncthreads();
    const int bglob = row0 >> 11;
    const int trow  = row0 & 2047;
    const float qs = (NB == 8) ? 0.03125f : 1.0f;   // fold 1/sqrt(1024) into Q

    // Q/K: d-permuted columns (pair interleave)
    #pragma unroll
    for (int nb = 0; nb < 8; nb++) {
        const int cm0 = nb * 8 + PPERM(2 * t4);
        const int cm1 = nb * 8 + PPERM(2 * t4 + 1);
        ES[(rb + grp) * 68 + cm0]     = u2f(tf32r(acc[nb][0] * qs));
        ES[(rb + grp) * 68 + cm1]     = u2f(tf32r(acc[nb][1] * qs));
        ES[(rb + grp + 8) * 68 + cm0] = u2f(tf32r(acc[nb][2] * qs));
        ES[(rb + grp + 8) * 68 + cm1] = u2f(tf32r(acc[nb][3] * qs));
    }
    __syncthreads();
    #pragma unroll
    for (int i = 0; i < 8; i++) {
        int f = tid + i * 256;
        int r = f >> 4, c4 = (f & 15) * 4;
        *(float4*)(T0 + (size_t)(row0 + r) * HS + c4) =
            *(const float4*)&ES[r * 68 + c4];
    }

    if (NB == 16) {   // V transposed via ES [h][r] s132; key-rows pair-interleaved
        __syncthreads();
        const int rpm = rb + PPERM(grp);
        #pragma unroll
        for (int nb = 0; nb < 8; nb++) {
            const int h2 = nb * 8 + 2 * t4;
            ES[h2 * 132 + rpm]           = u2f(tf32r(acc[8 + nb][0]));
            ES[(h2 + 1) * 132 + rpm]     = u2f(tf32r(acc[8 + nb][1]));
            ES[h2 * 132 + rpm + 8]       = u2f(tf32r(acc[8 + nb][2]));
            ES[(h2 + 1) * 132 + rpm + 8] = u2f(tf32r(acc[8 + nb][3]));
        }
        __syncthreads();
        #pragma unroll
        for (int i = 0; i < 8; i++) {
            int f = tid + i * 256;
            int h = f >> 5, r4 = (f & 31) * 4;
            *(float4*)(T1 + (size_t)(bglob * 64 + h) * SEQ + trow + r4) =
                *(const float4*)&ES[h * 132 + r4];
        }
    }
}

#define PROJ_SMB (4 * (2560 + 2 * 1152) * 4)   // 77824 B

__global__ __launch_bounds__(256, 2) void proj_kernel(
    const float* __restrict__ Xq, const float* __restrict__ Xkv)
{
    extern __shared__ float SM[];
    const int row0 = blockIdx.x * 128;
    if (blockIdx.y == 0)
        proj_body<8>(Xq, row0, SM, g_Q, (float*)0);
    else
        proj_body<16>(Xkv, row0, SM, g_K, g_Vt);
}

// ============================================================================
// Flash attention (byte-identical to the 176.1us best): warps 0-3 QK(kt)+exp
// (no max subtraction; logits bounded), warps 4-7 PV(kt-1). Pair-interleaved
// layouts -> all mma fragment loads are LDS.64.
// ============================================================================
#define KST 72
#define PST 68
#define AKS0 0
#define AKS1 4608
#define AVS0 9216
#define AVS1 13824
#define APS0 18432
#define APS1 22784
#define ALS  27136
#define ASMF 27200    // floats = 108800 B

__global__ __launch_bounds__(256, 2) void attn_kernel(float* __restrict__ out)
{
    extern __shared__ float sm[];
    const int tid  = threadIdx.x;
    const int wid  = tid >> 5;
    const int lane = tid & 31;
    const int grp  = lane >> 2;
    const int t4   = lane & 3;
    const int rb   = (wid & 3) << 4;
    const int r0   = rb + grp;

    const int b = blockIdx.y;
    const int qt = qt_map[blockIdx.x];
    const int qrow0 = qt * 64;

    const float* Qg = g_Q  + ((size_t)b * SEQ + qrow0) * HS;
    const float* Kg = g_K  + (size_t)b * SEQ * HS;
    const float* Vg = g_Vt + (size_t)(b * 64) * SEQ;

    const int fr  = tid >> 2;
    const int fcb = (tid & 3) * 4;

    // prologue: async K(0); Q staged sync into KS1; grab Q fragments
    #pragma unroll
    for (int i = 0; i < 4; i++) {
        int c = fcb + i * 16;
        cpa16(sm2u(sm + AKS0 + fr * KST + c), Kg + (size_t)fr * HS + c);
    }
    cpa_commit();
    #pragma unroll
    for (int i = 0; i < 4; i++) {
        int c = fcb + i * 16;
        *(float4*)&sm[AKS1 + fr * KST + c] = *(const float4*)(Qg + (size_t)fr * HS + c);
    }
    cpa_wait<0>();
    __syncthreads();

    u32 aq[8][4];
    if (wid < 4) {
        #pragma unroll
        for (int kk = 0; kk < 8; kk++) {
            const int d0 = kk * 8;
            u64 qa = *(const u64*)&sm[AKS1 + r0 * KST + d0 + 2 * t4];
            u64 qb = *(const u64*)&sm[AKS1 + (r0 + 8) * KST + d0 + 2 * t4];
            aq[kk][0] = lo32(qa);
            aq[kk][1] = lo32(qb);
            aq[kk][2] = hi32(qa);
            aq[kk][3] = hi32(qb);
        }
    }

    float acc[8][4];
    #pragma unroll
    for (int nb = 0; nb < 8; nb++)
        #pragma unroll
        for (int j = 0; j < 4; j++) acc[nb][j] = 0.f;
    float l0 = 0.f, l1 = 0.f;

    const int pc0 = PPERM(2 * t4);
    const int pc1 = PPERM(2 * t4 + 1);

    for (int kt = 0; kt <= qt; kt++) {
        cpa_wait<0>();
        __syncthreads();
        const int p = kt & 1;

        if (kt < qt) {
            float* ksn = sm + (p ? AKS0 : AKS1);
            #pragma unroll
            for (int i = 0; i < 4; i++) {
                int c = fcb + i * 16;
                cpa16(sm2u(ksn + fr * KST + c),
                      Kg + (size_t)((kt + 1) * 64 + fr) * HS + c);
            }
        }
        {
            float* vsn = sm + (p ? AVS1 : AVS0);
            #pragma unroll
            for (int i = 0; i < 4; i++) {
                int c = fcb + i * 16;
                cpa16(sm2u(vsn + fr * KST + c),
                      Vg + (size_t)fr * SEQ + kt * 64 + c);
            }
        }
        cpa_commit();

        if (wid < 4) {
            const float* KSp = sm + (p ? AKS1 : AKS0);
            float S[8][4];
            #pragma unroll
            for (int nb = 0; nb < 8; nb++)
                #pragma unroll
                for (int j = 0; j < 4; j++) S[nb][j] = 0.f;
            #pragma unroll
            for (int kk = 0; kk < 8; kk++) {
                const int d0 = kk * 8;
                #pragma unroll
                for (int nb = 0; nb < 8; nb++) {
                    u64 bb = *(const u64*)&KSp[(nb * 8 + grp) * KST + d0 + 2 * t4];
                    mma8(S[nb], aq[kk][0], aq[kk][1], aq[kk][2], aq[kk][3],
                         lo32(bb), hi32(bb));
                }
            }
            if (kt == qt) {
                #pragma unroll
                for (int nb = 0; nb < 8; nb++) {
                    int c0 = nb * 8 + 2 * t4;
                    if (c0     > r0)     S[nb][0] = -1e30f;
                    if (c0 + 1 > r0)     S[nb][1] = -1e30f;
                    if (c0     > r0 + 8) S[nb][2] = -1e30f;
                    if (c0 + 1 > r0 + 8) S[nb][3] = -1e30f;
                }
            }
            float* PSb = sm + (p ? APS1 : APS0);
            #pragma unroll
            for (int nb = 0; nb < 8; nb++) {
                u32 p0 = tf32r(__expf(S[nb][0]));
                u32 p1 = tf32r(__expf(S[nb][1]));
                u32 p2 = tf32r(__expf(S[nb][2]));
                u32 p3 = tf32r(__expf(S[nb][3]));
                l0 += u2f(p0) + u2f(p1);
                l1 += u2f(p2) + u2f(p3);
                PSb[r0 * PST + nb * 8 + pc0]       = u2f(p0);
                PSb[r0 * PST + nb * 8 + pc1]       = u2f(p1);
                PSb[(r0 + 8) * PST + nb * 8 + pc0] = u2f(p2);
                PSb[(r0 + 8) * PST + nb * 8 + pc1] = u2f(p3);
            }
        } else if (kt > 0) {
            const int q2 = p ^ 1;
            const float* PSb = sm + (q2 ? APS1 : APS0);
            const float* VSp = sm + (q2 ? AVS1 : AVS0);
            #pragma unroll
            for (int ks = 0; ks < 8; ks++) {
                const int k0 = ks * 8;
                u64 pa = *(const u64*)&PSb[r0 * PST + k0 + 2 * t4];
                u64 pb = *(const u64*)&PSb[(r0 + 8) * PST + k0 + 2 * t4];
                u32 a0 = lo32(pa), a1 = lo32(pb), a2 = hi32(pa), a3 = hi32(pb);
                #pragma unroll
                for (int nb = 0; nb < 8; nb++) {
                    u64 vv = *(const u64*)&VSp[(nb * 8 + grp) * KST + k0 + 2 * t4];
                    mma8(acc[nb], a0, a1, a2, a3, lo32(vv), hi32(vv));
                }
            }
        }
    }

    // drain: publish l, final PV(qt), normalize, store
    cpa_wait<0>();
    __syncthreads();
    if (wid < 4) {
        l0 += __shfl_xor_sync(0xffffffffu, l0, 1);
        l0 += __shfl_xor_sync(0xffffffffu, l0, 2);
        l1 += __shfl_xor_sync(0xffffffffu, l1, 1);
        l1 += __shfl_xor_sync(0xffffffffu, l1, 2);
        if (t4 == 0) {
            sm[ALS + r0]     = l0;
            sm[ALS + r0 + 8] = l1;
        }
    } else {
        const int q2 = qt & 1;
        const float* PSb = sm + (q2 ? APS1 : APS0);
        const float* VSp = sm + (q2 ? AVS1 : AVS0);
        #pragma unroll
        for (int ks = 0; ks < 8; ks++) {
            const int k0 = ks * 8;
            u64 pa = *(const u64*)&PSb[r0 * PST + k0 + 2 * t4];
            u64 pb = *(const u64*)&PSb[(r0 + 8) * PST + k0 + 2 * t4];
            u32 a0 = lo32(pa), a1 = lo32(pb), a2 = hi32(pa), a3 = hi32(pb);
            #pragma unroll
            for (int nb = 0; nb < 8; nb++) {
                u64 vv = *(const u64*)&VSp[(nb * 8 + grp) * KST + k0 + 2 * t4];
                mma8(acc[nb], a0, a1, a2, a3, lo32(vv), hi32(vv));
            }
        }
    }
    __syncthreads();
    if (wid >= 4) {
        const float inv0 = 1.0f / sm[ALS + r0];
        const float inv1 = 1.0f / sm[ALS + r0 + 8];
        float* o0 = out + ((size_t)b * SEQ + qrow0 + r0) * HS;
        float* o8 = o0 + 8 * HS;
        #pragma unroll
        for (int nb = 0; nb < 8; nb++) {
            *(u64*)(o0 + nb * 8 + 2 * t4) =
                pack2(acc[nb][0] * inv0, acc[nb][1] * inv0);
            *(u64*)(o8 + nb * 8 + 2 * t4) =
                pack2(acc[nb][2] * inv1, acc[nb][3] * inv1);
        }
    }
}

extern "C" void kernel_launch(void* const* d_in, const int* in_sizes, int n_in,
                              void* d_out, int out_size)
{
    (void)in_sizes; (void)n_in; (void)out_size;
    const float* index  = (const float*)d_in[0];
    const float* memory = (const float*)d_in[1];
    const float* Wq     = (const float*)d_in[2];
    const float* Wk     = (const float*)d_in[3];
    const float* Wv     = (const float*)d_in[4];
    float* out = (float*)d_out;

    cudaFuncSetAttribute(proj_kernel,
                         cudaFuncAttributeMaxDynamicSharedMemorySize, PROJ_SMB);
    cudaFuncSetAttribute(attn_kernel,
                         cudaFuncAttributeMaxDynamicSharedMemorySize, ASMF * 4);

    prep_w<<<256, 256>>>(Wq, Wk, Wv);
    proj_kernel<<<dim3(128, 2), 256, PROJ_SMB>>>(index, memory);
    attn_kernel<<<dim3(32, 8), 256, ASMF * 4>>>(out);
}

// round 16
// speedup vs baseline: 1.7961x; 1.2671x over previous
#include <cuda_runtime.h>
#include <cuda_fp16.h>

#define BATCH 8
#define SEQ   2048
#define EMB   1024
#define HS    64
#define MROWS (BATCH*SEQ)

typedef unsigned long long u64;
typedef unsigned int u32;

// fp16 tensors. Q pre-scaled by 1/32. Q,K natural rows [b][t][dperm16]
// (d interleaved [0,1,8,9,2,3,10,11,...] per 16-group); V transposed
// [b*64+h][tperm16] (same 16-interleave on t).
__device__ __half g_Q16[(size_t)MROWS * HS];
__device__ __half g_K16[(size_t)MROWS * HS];
__device__ __half g_V16[(size_t)MROWS * HS];
// Pre-rounded (tf32) weights for the fp32->tf32 projection mma, [k][n].
__device__ float g_Wqr[EMB * HS];
__device__ float g_Wkr[EMB * HS];
__device__ float g_Wvh[EMB * HS];

__device__ const int qt_map[32] = {
    0,4,8,12,29,25,21,17,1,5,9,13,28,24,20,16,
    2,6,10,14,31,27,23,19,3,7,11,15,30,26,22,18};

__device__ __forceinline__ u64 pack2(float x, float y) {
    u64 r; asm("mov.b64 %0, {%1, %2};" : "=l"(r) : "f"(x), "f"(y)); return r;
}
__device__ __forceinline__ u32 tf32r(float x) {
    u32 r; asm("cvt.rna.tf32.f32 %0, %1;" : "=r"(r) : "f"(x)); return r;
}
__device__ __forceinline__ u32 f2u(float x) { return __float_as_uint(x); }
__device__ __forceinline__ float u2f(u32 x) { return __uint_as_float(x); }
__device__ __forceinline__ u32 lo32(u64 v) { return (u32)v; }
__device__ __forceinline__ u32 hi32(u64 v) { return (u32)(v >> 32); }
// 16-group interleave: logical k (0..15) -> mem position
__device__ __forceinline__ int pp16(int l) {
    return (((l & 7) >> 1) << 2) + (l & 1) + ((l & 8) ? 2 : 0);
}
__device__ __forceinline__ u32 h2u(__half2 h) { return *(u32*)&h; }

// tf32 m16n8k8 (projection)
__device__ __forceinline__ void mma8(float* c, u32 a0, u32 a1, u32 a2, u32 a3,
                                     u32 b0, u32 b1) {
    asm volatile(
        "mma.sync.aligned.m16n8k8.row.col.f32.tf32.tf32.f32 "
        "{%0,%1,%2,%3}, {%4,%5,%6,%7}, {%8,%9}, {%0,%1,%2,%3};"
        : "+f"(c[0]), "+f"(c[1]), "+f"(c[2]), "+f"(c[3])
        : "r"(a0), "r"(a1), "r"(a2), "r"(a3), "r"(b0), "r"(b1));
}
// fp16 m16n8k16, fp32 accum (attention)
__device__ __forceinline__ void mma16(float* c, u32 a0, u32 a1, u32 a2, u32 a3,
                                      u32 b0, u32 b1) {
    asm volatile(
        "mma.sync.aligned.m16n8k16.row.col.f32.f16.f16.f32 "
        "{%0,%1,%2,%3}, {%4,%5,%6,%7}, {%8,%9}, {%0,%1,%2,%3};"
        : "+f"(c[0]), "+f"(c[1]), "+f"(c[2]), "+f"(c[3])
        : "r"(a0), "r"(a1), "r"(a2), "r"(a3), "r"(b0), "r"(b1));
}
__device__ __forceinline__ u32 sm2u(const void* p) {
    return (u32)__cvta_generic_to_shared(p);
}
__device__ __forceinline__ void cpa16(u32 d, const void* s) {
    asm volatile("cp.async.cg.shared.global [%0], [%1], 16;" :: "r"(d), "l"(s));
}
__device__ __forceinline__ void cpa_commit() {
    asm volatile("cp.async.commit_group;");
}
template<int N> __device__ __forceinline__ void cpa_wait() {
    asm volatile("cp.async.wait_group %0;" :: "n"(N));
}

// ============================================================================
// prep_w: tf32-round weights once (for the projection mma).
// ============================================================================
__global__ void prep_w(const float* __restrict__ Wq, const float* __restrict__ Wk,
                       const float* __restrict__ Wv)
{
    int i = blockIdx.x * 256 + threadIdx.x;
    g_Wqr[i] = u2f(tf32r(Wq[i]));
    g_Wkr[i] = u2f(tf32r(Wk[i]));
    g_Wvh[i] = u2f(tf32r(Wv[i]));
}

// ============================================================================
// Projection: mainloop identical to the 160.9us best (BK=16, 4-stage cp.async
// ring, tf32 mma, X [r][k] s20, W [k][n] s72). Epilogues now emit fp16 with
// the 16-group interleave: Q/K natural rows [t][dperm16]; V transposed
// [h][tperm16]. NB=8: Q (x 1/32). NB=16: K and V (single tf32 mma).
// ============================================================================
template<int NB>
__device__ __forceinline__ void proj_body(
    const float* __restrict__ X, int row0, float* SM,
    __half* T0, __half* T1)
{
    const int NW  = (NB == 8) ? 1 : 2;
    const int SS  = 2560 + NW * 1152;
    __half* ESh = (__half*)SM;

    const int tid  = threadIdx.x;
    const int wid  = tid >> 5;
    const int lane = tid & 31;
    const int grp  = lane >> 2;
    const int t4   = lane & 3;
    const int rb   = wid << 4;

    const int xr = tid >> 2;
    const int xc = (tid & 3) * 4;
    const int wk = tid >> 4;
    const int wn = (tid & 15) * 4;

    float acc[NB][4];
    #pragma unroll
    for (int nb = 0; nb < NB; nb++)
        #pragma unroll
        for (int j = 0; j < 4; j++) acc[nb][j] = 0.f;

    auto issue = [&](int st, int k0) {
        float* xs = SM + st * SS;
        #pragma unroll
        for (int j = 0; j < 2; j++) {
            int r = xr + j * 64;
            cpa16(sm2u(xs + r * 20 + xc), X + (size_t)(row0 + r) * EMB + k0 + xc);
        }
        float* ws = xs + 2560;
        if (NB == 8) {
            cpa16(sm2u(ws + wk * 72 + wn), g_Wqr + (size_t)(k0 + wk) * HS + wn);
        } else {
            cpa16(sm2u(ws + wk * 72 + wn),
                  g_Wkr + (size_t)(k0 + wk) * HS + wn);
            cpa16(sm2u(ws + 1152 + wk * 72 + wn),
                  g_Wvh + (size_t)(k0 + wk) * HS + wn);
        }
        cpa_commit();
    };
    issue(0, 0); issue(1, 16); issue(2, 32);

    for (int t = 0; t < 64; t++) {
        if (t <= 61)      cpa_wait<2>();
        else if (t == 62) cpa_wait<1>();
        else              cpa_wait<0>();
        __syncthreads();
        if (t + 3 < 64) issue((t + 3) & 3, (t + 3) * 16);

        const float* xs = SM + (t & 3) * SS;
        const float* ws = xs + 2560;
        #pragma unroll
        for (int ks = 0; ks < 2; ks++) {
            const int k0 = ks * 8;
            u32 ah0 = tf32r(xs[(rb + grp) * 20 + k0 + t4]);
            u32 ah1 = tf32r(xs[(rb + grp + 8) * 20 + k0 + t4]);
            u32 ah2 = tf32r(xs[(rb + grp) * 20 + k0 + t4 + 4]);
            u32 ah3 = tf32r(xs[(rb + grp + 8) * 20 + k0 + t4 + 4]);
            #pragma unroll
            for (int nb = 0; nb < 8; nb++) {
                const int n = nb * 8 + grp;
                u32 b0 = f2u(ws[(k0 + t4) * 72 + n]);
                u32 b1 = f2u(ws[(k0 + t4 + 4) * 72 + n]);
                mma8(acc[nb], ah0, ah1, ah2, ah3, b0, b1);
                if (NB == 16) {
                    u32 bh0 = f2u(ws[1152 + (k0 + t4) * 72 + n]);
                    u32 bh1 = f2u(ws[1152 + (k0 + t4 + 4) * 72 + n]);
                    mma8(acc[8 + nb], ah0, ah1, ah2, ah3, bh0, bh1);
                }
            }
        }
    }

    // ---- epilogue (ring drained) ----
    __syncthreads();
    const int bglob = row0 >> 11;
    const int trow  = row0 & 2047;
    const float qs = (NB == 8) ? 0.03125f : 1.0f;

    // Q/K: fp16, d interleaved: cols (c, c+1) -> positions (pos, pos+1)
    #pragma unroll
    for (int nb = 0; nb < 8; nb++) {
        const int pos = ((nb >> 1) << 4) + 4 * t4 + ((nb & 1) << 1);
        __half2 v01 = __floats2half2_rn(acc[nb][0] * qs, acc[nb][1] * qs);
        __half2 v23 = __floats2half2_rn(acc[nb][2] * qs, acc[nb][3] * qs);
        *(u32*)&ESh[(rb + grp) * 72 + pos]     = h2u(v01);
        *(u32*)&ESh[(rb + grp + 8) * 72 + pos] = h2u(v23);
    }
    __syncthreads();
    #pragma unroll
    for (int i = 0; i < 4; i++) {
        int f = tid + i * 256;          // 128 rows x 8 chunks of 8 halves
        int r = f >> 3, c8 = (f & 7) * 8;
        *(float4*)(T0 + (size_t)(row0 + r) * HS + c8) =
            *(const float4*)&ESh[r * 72 + c8];
    }

    if (NB == 16) {   // V: fp16 transposed [h][tperm16], via ESh [h][128+8]
        __syncthreads();
        const int k0l = rb + grp;
        const int kp0 = (k0l & ~15) + pp16(k0l & 15);
        const int k8l = rb + grp + 8;
        const int kp8 = (k8l & ~15) + pp16(k8l & 15);
        #pragma unroll
        for (int nb = 0; nb < 8; nb++) {
            const int h2 = nb * 8 + 2 * t4;
            ESh[h2 * 136 + kp0]       = __float2half_rn(acc[8 + nb][0]);
            ESh[(h2 + 1) * 136 + kp0] = __float2half_rn(acc[8 + nb][1]);
            ESh[h2 * 136 + kp8]       = __float2half_rn(acc[8 + nb][2]);
            ESh[(h2 + 1) * 136 + kp8] = __float2half_rn(acc[8 + nb][3]);
        }
        __syncthreads();
        #pragma unroll
        for (int i = 0; i < 4; i++) {
            int f = tid + i * 256;      // 64 rows x 16 chunks of 8 halves
            int h = f >> 4, c8 = (f & 15) * 8;
            *(float4*)(T1 + (size_t)(bglob * 64 + h) * SEQ + trow + c8) =
                *(const float4*)&ESh[h * 136 + c8];
        }
    }
}

#define PROJ_SMB (4 * (2560 + 2 * 1152) * 4)   // 77824 B

__global__ __launch_bounds__(256, 2) void proj_kernel(
    const float* __restrict__ Xq, const float* __restrict__ Xkv)
{
    extern __shared__ float SM[];
    const int row0 = blockIdx.x * 128;
    if (blockIdx.y == 0)
        proj_body<8>(Xq, row0, SM, g_Q16, (__half*)0);
    else
        proj_body<16>(Xkv, row0, SM, g_K16, g_V16);
}

// ============================================================================
// Flash attention, fp16 m16n8k16: warps 0-3 QK(kt)+exp, warps 4-7 PV(kt-1).
// 16-interleaved layouts -> every fragment is one LDS.64. Strides 80 halves
// (conflict-free LDS.64 phases). All offsets in halves.
// ============================================================================
#define KST16 80
#define HKS0  0
#define HKS1  5120
#define HVS0  10240
#define HVS1  15360
#define HPS0  20480
#define HPS1  25600
#define ALSB  61440                 // byte offset of l array (64 floats)
#define ASMB  (ALSB + 256)

__global__ __launch_bounds__(256, 2) void attn_kernel(float* __restrict__ out)
{
    extern __shared__ __half smh[];
    float* ALSf = (float*)((char*)smh + ALSB);

    const int tid  = threadIdx.x;
    const int wid  = tid >> 5;
    const int lane = tid & 31;
    const int grp  = lane >> 2;
    const int t4   = lane & 3;
    const int rb   = (wid & 3) << 4;
    const int r0   = rb + grp;

    const int b = blockIdx.y;
    const int qt = qt_map[blockIdx.x];
    const int qrow0 = qt * 64;

    const __half* Qg = g_Q16 + ((size_t)b * SEQ + qrow0) * HS;
    const __half* Kg = g_K16 + (size_t)b * SEQ * HS;
    const __half* Vg = g_V16 + (size_t)(b * 64) * SEQ;

    const int fr = tid >> 2;            // fill row 0..63
    const int fq = (tid & 3) * 16;      // fill half-offset base

    // prologue: async K(0); Q staged sync into HKS1; grab Q fragments
    #pragma unroll
    for (int i = 0; i < 2; i++)
        cpa16(sm2u(&smh[HKS0 + fr * KST16 + fq + i * 8]),
              Kg + (size_t)fr * HS + fq + i * 8);
    cpa_commit();
    #pragma unroll
    for (int i = 0; i < 2; i++)
        *(float4*)&smh[HKS1 + fr * KST16 + fq + i * 8] =
            *(const float4*)(Qg + (size_t)fr * HS + fq + i * 8);
    cpa_wait<0>();
    __syncthreads();

    u32 aq[4][4];
    if (wid < 4) {
        #pragma unroll
        for (int kg = 0; kg < 4; kg++) {
            u64 qa = *(const u64*)&smh[HKS1 + r0 * KST16 + kg * 16 + 4 * t4];
            u64 qb = *(const u64*)&smh[HKS1 + (r0 + 8) * KST16 + kg * 16 + 4 * t4];
            aq[kg][0] = lo32(qa);   // (r0,   k01)
            aq[kg][1] = lo32(qb);   // (r0+8, k01)
            aq[kg][2] = hi32(qa);   // (r0,   k89)
            aq[kg][3] = hi32(qb);   // (r0+8, k89)
        }
    }

    float acc[8][4];
    #pragma unroll
    for (int nb = 0; nb < 8; nb++)
        #pragma unroll
        for (int j = 0; j < 4; j++) acc[nb][j] = 0.f;
    float l0 = 0.f, l1 = 0.f;

    for (int kt = 0; kt <= qt; kt++) {
        cpa_wait<0>();            // K(kt), V(kt-1) landed
        __syncthreads();          // visible; P(kt-1) visible
        const int p = kt & 1;

        if (kt < qt) {
            const int ksn = p ? HKS0 : HKS1;
            #pragma unroll
            for (int i = 0; i < 2; i++)
                cpa16(sm2u(&smh[ksn + fr * KST16 + fq + i * 8]),
                      Kg + (size_t)((kt + 1) * 64 + fr) * HS + fq + i * 8);
        }
        {
            const int vsn = p ? HVS1 : HVS0;
            #pragma unroll
            for (int i = 0; i < 2; i++)
                cpa16(sm2u(&smh[vsn + fr * KST16 + fq + i * 8]),
                      Vg + (size_t)fr * SEQ + kt * 64 + fq + i * 8);
        }
        cpa_commit();

        if (wid < 4) {
            // ---- QK(kt) + exp (no max subtraction; logits bounded) ----
            const int kso = p ? HKS1 : HKS0;
            float S[8][4];
            #pragma unroll
            for (int nb = 0; nb < 8; nb++)
                #pragma unroll
                for (int j = 0; j < 4; j++) S[nb][j] = 0.f;
            #pragma unroll
            for (int kg = 0; kg < 4; kg++) {
                #pragma unroll
                for (int nb = 0; nb < 8; nb++) {
                    u64 bb = *(const u64*)
                        &smh[kso + (nb * 8 + grp) * KST16 + kg * 16 + 4 * t4];
                    mma16(S[nb], aq[kg][0], aq[kg][1], aq[kg][2], aq[kg][3],
                          lo32(bb), hi32(bb));
                }
            }
            if (kt == qt) {   // causal mask (natural cols)
                #pragma unroll
                for (int nb = 0; nb < 8; nb++) {
                    int c0 = nb * 8 + 2 * t4;
                    if (c0     > r0)     S[nb][0] = -1e30f;
                    if (c0 + 1 > r0)     S[nb][1] = -1e30f;
                    if (c0     > r0 + 8) S[nb][2] = -1e30f;
                    if (c0 + 1 > r0 + 8) S[nb][3] = -1e30f;
                }
            }
            const int pso = p ? HPS1 : HPS0;
            #pragma unroll
            for (int nb = 0; nb < 8; nb++) {
                float p0 = __expf(S[nb][0]);
                float p1 = __expf(S[nb][1]);
                float p2 = __expf(S[nb][2]);
                float p3 = __expf(S[nb][3]);
                l0 += p0 + p1;
                l1 += p2 + p3;
                const int pp = ((nb >> 1) << 4) + 4 * t4 + ((nb & 1) << 1);
                *(u32*)&smh[pso + r0 * KST16 + pp] =
                    h2u(__floats2half2_rn(p0, p1));
                *(u32*)&smh[pso + (r0 + 8) * KST16 + pp] =
                    h2u(__floats2half2_rn(p2, p3));
            }
        } else if (kt > 0) {
            // ---- PV(kt-1) ----
            const int q2 = p ^ 1;
            const int pso = q2 ? HPS1 : HPS0;
            const int vso = q2 ? HVS1 : HVS0;
            #pragma unroll
            for (int kg = 0; kg < 4; kg++) {
                u64 pa = *(const u64*)&smh[pso + r0 * KST16 + kg * 16 + 4 * t4];
                u64 pb = *(const u64*)&smh[pso + (r0 + 8) * KST16 + kg * 16 + 4 * t4];
                #pragma unroll
                for (int nb = 0; nb < 8; nb++) {
                    u64 vv = *(const u64*)
                        &smh[vso + (nb * 8 + grp) * KST16 + kg * 16 + 4 * t4];
                    mma16(acc[nb], lo32(pa), lo32(pb), hi32(pa), hi32(pb),
                          lo32(vv), hi32(vv));
                }
            }
        }
    }

    // drain: publish l, final PV(qt), normalize, store
    cpa_wait<0>();
    __syncthreads();
    if (wid < 4) {
        l0 += __shfl_xor_sync(0xffffffffu, l0, 1);
        l0 += __shfl_xor_sync(0xffffffffu, l0, 2);
        l1 += __shfl_xor_sync(0xffffffffu, l1, 1);
        l1 += __shfl_xor_sync(0xffffffffu, l1, 2);
        if (t4 == 0) {
            ALSf[r0]     = l0;
            ALSf[r0 + 8] = l1;
        }
    } else {
        const int q2 = qt & 1;
        const int pso = q2 ? HPS1 : HPS0;
        const int vso = q2 ? HVS1 : HVS0;
        #pragma unroll
        for (int kg = 0; kg < 4; kg++) {
            u64 pa = *(const u64*)&smh[pso + r0 * KST16 + kg * 16 + 4 * t4];
            u64 pb = *(const u64*)&smh[pso + (r0 + 8) * KST16 + kg * 16 + 4 * t4];
            #pragma unroll
            for (int nb = 0; nb < 8; nb++) {
                u64 vv = *(const u64*)
                    &smh[vso + (nb * 8 + grp) * KST16 + kg * 16 + 4 * t4];
                mma16(acc[nb], lo32(pa), lo32(pb), hi32(pa), hi32(pb),
                      lo32(vv), hi32(vv));
            }
        }
    }
    __syncthreads();
    if (wid >= 4) {
        const float inv0 = 1.0f / ALSf[r0];
        const float inv1 = 1.0f / ALSf[r0 + 8];
        float* o0 = out + ((size_t)b * SEQ + qrow0 + r0) * HS;
        float* o8 = o0 + 8 * HS;
        #pragma unroll
        for (int nb = 0; nb < 8; nb++) {
            *(u64*)(o0 + nb * 8 + 2 * t4) =
                pack2(acc[nb][0] * inv0, acc[nb][1] * inv0);
            *(u64*)(o8 + nb * 8 + 2 * t4) =
                pack2(acc[nb][2] * inv1, acc[nb][3] * inv1);
        }
    }
}

extern "C" void kernel_launch(void* const* d_in, const int* in_sizes, int n_in,
                              void* d_out, int out_size)
{
    (void)in_sizes; (void)n_in; (void)out_size;
    const float* index  = (const float*)d_in[0];
    const float* memory = (const float*)d_in[1];
    const float* Wq     = (const float*)d_in[2];
    const float* Wk     = (const float*)d_in[3];
    const float* Wv     = (const float*)d_in[4];
    float* out = (float*)d_out;

    cudaFuncSetAttribute(proj_kernel,
                         cudaFuncAttributeMaxDynamicSharedMemorySize, PROJ_SMB);
    cudaFuncSetAttribute(attn_kernel,
                         cudaFuncAttributeMaxDynamicSharedMemorySize, ASMB);

    prep_w<<<256, 256>>>(Wq, Wk, Wv);
    proj_kernel<<<dim3(128, 2), 256, PROJ_SMB>>>(index, memory);
    attn_kernel<<<dim3(32, 8), 256, ASMB>>>(out);
}

// round 17
// speedup vs baseline: 2.2272x; 1.2400x over previous
#include <cuda_runtime.h>
#include <cuda_fp16.h>

#define BATCH 8
#define SEQ   2048
#define EMB   1024
#define HS    64
#define MROWS (BATCH*SEQ)

typedef unsigned long long u64;
typedef unsigned int u32;

// fp16 tensors. Q pre-scaled by 1/32 (folded into Wq16). Q,K natural rows
// [b][t][dperm16] (d interleaved [0,1,8,9,2,3,10,11,...] per 16-group);
// V transposed [b*64+h][tperm16] (same 16-interleave on t).
__device__ __half g_Q16[(size_t)MROWS * HS];
__device__ __half g_K16[(size_t)MROWS * HS];
__device__ __half g_V16[(size_t)MROWS * HS];
// fp16 weights, TRANSPOSED [n][kperm16] (64 rows x 1024 k, 16-interleaved k).
__device__ __half g_Wq16[HS * EMB];
__device__ __half g_Wk16[HS * EMB];
__device__ __half g_Wv16[HS * EMB];

__device__ const int qt_map[32] = {
    0,4,8,12,29,25,21,17,1,5,9,13,28,24,20,16,
    2,6,10,14,31,27,23,19,3,7,11,15,30,26,22,18};

__device__ __forceinline__ u64 pack2(float x, float y) {
    u64 r; asm("mov.b64 %0, {%1, %2};" : "=l"(r) : "f"(x), "f"(y)); return r;
}
__device__ __forceinline__ u32 lo32(u64 v) { return (u32)v; }
__device__ __forceinline__ u32 hi32(u64 v) { return (u32)(v >> 32); }
// 16-group interleave: logical k -> mem position
__device__ __forceinline__ int pp16(int l) {
    return (((l & 7) >> 1) << 2) + (l & 1) + ((l & 8) ? 2 : 0);
}
__device__ __forceinline__ u32 h2u(__half2 h) { return *(u32*)&h; }

// fp16 m16n8k16, fp32 accum
__device__ __forceinline__ void mma16(float* c, u32 a0, u32 a1, u32 a2, u32 a3,
                                      u32 b0, u32 b1) {
    asm volatile(
        "mma.sync.aligned.m16n8k16.row.col.f32.f16.f16.f32 "
        "{%0,%1,%2,%3}, {%4,%5,%6,%7}, {%8,%9}, {%0,%1,%2,%3};"
        : "+f"(c[0]), "+f"(c[1]), "+f"(c[2]), "+f"(c[3])
        : "r"(a0), "r"(a1), "r"(a2), "r"(a3), "r"(b0), "r"(b1));
}
__device__ __forceinline__ u32 sm2u(const void* p) {
    return (u32)__cvta_generic_to_shared(p);
}
__device__ __forceinline__ void cpa16(u32 d, const void* s) {
    asm volatile("cp.async.cg.shared.global [%0], [%1], 16;" :: "r"(d), "l"(s));
}
__device__ __forceinline__ void cpa_commit() {
    asm volatile("cp.async.commit_group;");
}
template<int N> __device__ __forceinline__ void cpa_wait() {
    asm volatile("cp.async.wait_group %0;" :: "n"(N));
}

// ============================================================================
// prep_w: convert weights to fp16, transpose to [n][k], 16-interleave k.
// Wq additionally scaled by 1/32 (exact). Block = 16 k x 64 n.
// ============================================================================
__global__ void prep_w(const float* __restrict__ Wq, const float* __restrict__ Wk,
                       const float* __restrict__ Wv)
{
    __shared__ __half S[3][16][68];
    const int tid = threadIdx.x;
    const int k0 = blockIdx.x * 16;
    {
        const int kk = tid >> 4, n4 = (tid & 15) * 4;
        float4 q = *(const float4*)(Wq + (size_t)(k0 + kk) * HS + n4);
        float4 k = *(const float4*)(Wk + (size_t)(k0 + kk) * HS + n4);
        float4 v = *(const float4*)(Wv + (size_t)(k0 + kk) * HS + n4);
        #pragma unroll
        for (int j = 0; j < 4; j++) {
            S[0][kk][n4 + j] = __float2half_rn((&q.x)[j] * 0.03125f);
            S[1][kk][n4 + j] = __float2half_rn((&k.x)[j]);
            S[2][kk][n4 + j] = __float2half_rn((&v.x)[j]);
        }
    }
    __syncthreads();
    const int n = tid >> 2, j4 = (tid & 3) * 4;
    __half* dst[3] = { g_Wq16, g_Wk16, g_Wv16 };
    #pragma unroll
    for (int w = 0; w < 3; w++) {
        __half tmp[4];
        #pragma unroll
        for (int i = 0; i < 4; i++) {
            int p = j4 + i;
            int a = p >> 2, bb = p & 3;
            int l = ((bb & 2) << 2) | (a << 1) | (bb & 1);   // inverse of pp16
            tmp[i] = S[w][l][n];
        }
        *(u64*)(dst[w] + (size_t)n * EMB + k0 + j4) = *(u64*)tmp;
    }
}

// ============================================================================
// Projection, fp16 m16n8k16: BK=16 (one mma16 per nb per iter), 4-stage
// cp.async ring. X fp32 [r][k] STRIDE 24 (conflict-free float2 A-loads,
// converted to fp16 on the fly); W fp16 [n][k16] stride 16 (one LDS.64 per
// B-fragment, bank = 4grp+t4 all distinct). NB=8: Q -> natural rows.
// NB=16: K -> natural rows, V -> transposed. fp16 epilogues, 16-interleaved.
// ============================================================================
template<int NB>
__device__ __forceinline__ void proj_body(
    const float* __restrict__ X, int row0, float* SM,
    __half* T0, __half* T1)
{
    const int NW = (NB == 8) ? 1 : 2;
    const int SS = 3072 + NW * 512;      // stage floats (X 3072 + W 512/region)
    __half* ESh = (__half*)SM;

    const int tid  = threadIdx.x;
    const int wid  = tid >> 5;
    const int lane = tid & 31;
    const int grp  = lane >> 2;
    const int t4   = lane & 3;
    const int rb   = wid << 4;

    const int xr = tid >> 2;             // X fill row (+64)
    const int xc = (tid & 3) * 4;        // X fill k chunk

    float acc[NB][4];
    #pragma unroll
    for (int nb = 0; nb < NB; nb++)
        #pragma unroll
        for (int j = 0; j < 4; j++) acc[nb][j] = 0.f;

    auto issue = [&](int st, int k0) {
        float* xs = SM + st * SS;
        #pragma unroll
        for (int j = 0; j < 2; j++) {
            int r = xr + j * 64;
            cpa16(sm2u(xs + r * 24 + xc), X + (size_t)(row0 + r) * EMB + k0 + xc);
        }
        __half* ws = (__half*)(xs + 3072);
        if (NB == 8) {
            if (tid < 128) {
                int wr = tid >> 1, wc = tid & 1;
                cpa16(sm2u(ws + wr * 16 + wc * 8),
                      g_Wq16 + (size_t)wr * EMB + k0 + wc * 8);
            }
        } else {
            if (tid < 128) {
                int wr = tid >> 1, wc = tid & 1;
                cpa16(sm2u(ws + wr * 16 + wc * 8),
                      g_Wk16 + (size_t)wr * EMB + k0 + wc * 8);
            } else {
                int q = tid - 128;
                int wr = q >> 1, wc = q & 1;
                cpa16(sm2u(ws + 1024 + wr * 16 + wc * 8),
                      g_Wv16 + (size_t)wr * EMB + k0 + wc * 8);
            }
        }
        cpa_commit();
    };
    issue(0, 0); issue(1, 16); issue(2, 32);

    for (int t = 0; t < 64; t++) {
        if (t <= 61)      cpa_wait<2>();
        else if (t == 62) cpa_wait<1>();
        else              cpa_wait<0>();
        __syncthreads();
        if (t + 3 < 64) issue((t + 3) & 3, (t + 3) * 16);

        const float* xs = SM + (t & 3) * SS;
        const __half* ws = (const __half*)(xs + 3072);

        float2 xa = *(const float2*)&xs[(rb + grp) * 24 + 2 * t4];
        float2 xb = *(const float2*)&xs[(rb + grp + 8) * 24 + 2 * t4];
        float2 xc2 = *(const float2*)&xs[(rb + grp) * 24 + 2 * t4 + 8];
        float2 xd = *(const float2*)&xs[(rb + grp + 8) * 24 + 2 * t4 + 8];
        u32 a0 = h2u(__floats2half2_rn(xa.x, xa.y));
        u32 a1 = h2u(__floats2half2_rn(xb.x, xb.y));
        u32 a2 = h2u(__floats2half2_rn(xc2.x, xc2.y));
        u32 a3 = h2u(__floats2half2_rn(xd.x, xd.y));

        #pragma unroll
        for (int nb = 0; nb < 8; nb++) {
            const int n = nb * 8 + grp;
            u64 wb = *(const u64*)&ws[n * 16 + 4 * t4];
            mma16(acc[nb], a0, a1, a2, a3, lo32(wb), hi32(wb));
            if (NB == 16) {
                u64 wv = *(const u64*)&ws[1024 + n * 16 + 4 * t4];
                mma16(acc[8 + nb], a0, a1, a2, a3, lo32(wv), hi32(wv));
            }
        }
    }

    // ---- epilogue (ring drained: wait<0> ran at t=63) ----
    __syncthreads();
    const int bglob = row0 >> 11;
    const int trow  = row0 & 2047;

    // Q/K: fp16, d interleaved: cols (c, c+1) -> positions (pos, pos+1)
    #pragma unroll
    for (int nb = 0; nb < 8; nb++) {
        const int pos = ((nb >> 1) << 4) + 4 * t4 + ((nb & 1) << 1);
        __half2 v01 = __floats2half2_rn(acc[nb][0], acc[nb][1]);
        __half2 v23 = __floats2half2_rn(acc[nb][2], acc[nb][3]);
        *(u32*)&ESh[(rb + grp) * 72 + pos]     = h2u(v01);
        *(u32*)&ESh[(rb + grp + 8) * 72 + pos] = h2u(v23);
    }
    __syncthreads();
    #pragma unroll
    for (int i = 0; i < 4; i++) {
        int f = tid + i * 256;
        int r = f >> 3, c8 = (f & 7) * 8;
        *(float4*)(T0 + (size_t)(row0 + r) * HS + c8) =
            *(const float4*)&ESh[r * 72 + c8];
    }

    if (NB == 16) {   // V: fp16 transposed [h][tperm16]
        __syncthreads();
        const int k0l = rb + grp;
        const int kp0 = (k0l & ~15) + pp16(k0l & 15);
        const int k8l = rb + grp + 8;
        const int kp8 = (k8l & ~15) + pp16(k8l & 15);
        #pragma unroll
        for (int nb = 0; nb < 8; nb++) {
            const int h2 = nb * 8 + 2 * t4;
            ESh[h2 * 136 + kp0]       = __float2half_rn(acc[8 + nb][0]);
            ESh[(h2 + 1) * 136 + kp0] = __float2half_rn(acc[8 + nb][1]);
            ESh[h2 * 136 + kp8]       = __float2half_rn(acc[8 + nb][2]);
            ESh[(h2 + 1) * 136 + kp8] = __float2half_rn(acc[8 + nb][3]);
        }
        __syncthreads();
        #pragma unroll
        for (int i = 0; i < 4; i++) {
            int f = tid + i * 256;
            int h = f >> 4, c8 = (f & 15) * 8;
            *(float4*)(T1 + (size_t)(bglob * 64 + h) * SEQ + trow + c8) =
                *(const float4*)&ESh[h * 136 + c8];
        }
    }
}

#define PROJ_SMB (4 * (3072 + 2 * 512) * 4)   // 65536 B

__global__ __launch_bounds__(256, 2) void proj_kernel(
    const float* __restrict__ Xq, const float* __restrict__ Xkv)
{
    extern __shared__ float SM[];
    const int row0 = blockIdx.x * 128;
    if (blockIdx.y == 0)
        proj_body<8>(Xq, row0, SM, g_Q16, (__half*)0);
    else
        proj_body<16>(Xkv, row0, SM, g_K16, g_V16);
}

// ============================================================================
// Flash attention (byte-identical to the 127.0us best), fp16 m16n8k16:
// warps 0-3 QK(kt)+exp, warps 4-7 PV(kt-1). 16-interleaved layouts ->
// every fragment is one LDS.64. Strides 80 halves. All offsets in halves.
// ============================================================================
#define KST16 80
#define HKS0  0
#define HKS1  5120
#define HVS0  10240
#define HVS1  15360
#define HPS0  20480
#define HPS1  25600
#define ALSB  61440
#define ASMB  (ALSB + 256)

__global__ __launch_bounds__(256, 2) void attn_kernel(float* __restrict__ out)
{
    extern __shared__ __half smh[];
    float* ALSf = (float*)((char*)smh + ALSB);

    const int tid  = threadIdx.x;
    const int wid  = tid >> 5;
    const int lane = tid & 31;
    const int grp  = lane >> 2;
    const int t4   = lane & 3;
    const int rb   = (wid & 3) << 4;
    const int r0   = rb + grp;

    const int b = blockIdx.y;
    const int qt = qt_map[blockIdx.x];
    const int qrow0 = qt * 64;

    const __half* Qg = g_Q16 + ((size_t)b * SEQ + qrow0) * HS;
    const __half* Kg = g_K16 + (size_t)b * SEQ * HS;
    const __half* Vg = g_V16 + (size_t)(b * 64) * SEQ;

    const int fr = tid >> 2;
    const int fq = (tid & 3) * 16;

    #pragma unroll
    for (int i = 0; i < 2; i++)
        cpa16(sm2u(&smh[HKS0 + fr * KST16 + fq + i * 8]),
              Kg + (size_t)fr * HS + fq + i * 8);
    cpa_commit();
    #pragma unroll
    for (int i = 0; i < 2; i++)
        *(float4*)&smh[HKS1 + fr * KST16 + fq + i * 8] =
            *(const float4*)(Qg + (size_t)fr * HS + fq + i * 8);
    cpa_wait<0>();
    __syncthreads();

    u32 aq[4][4];
    if (wid < 4) {
        #pragma unroll
        for (int kg = 0; kg < 4; kg++) {
            u64 qa = *(const u64*)&smh[HKS1 + r0 * KST16 + kg * 16 + 4 * t4];
            u64 qb = *(const u64*)&smh[HKS1 + (r0 + 8) * KST16 + kg * 16 + 4 * t4];
            aq[kg][0] = lo32(qa);
            aq[kg][1] = lo32(qb);
            aq[kg][2] = hi32(qa);
            aq[kg][3] = hi32(qb);
        }
    }

    float acc[8][4];
    #pragma unroll
    for (int nb = 0; nb < 8; nb++)
        #pragma unroll
        for (int j = 0; j < 4; j++) acc[nb][j] = 0.f;
    float l0 = 0.f, l1 = 0.f;

    for (int kt = 0; kt <= qt; kt++) {
        cpa_wait<0>();
        __syncthreads();
        const int p = kt & 1;

        if (kt < qt) {
            const int ksn = p ? HKS0 : HKS1;
            #pragma unroll
            for (int i = 0; i < 2; i++)
                cpa16(sm2u(&smh[ksn + fr * KST16 + fq + i * 8]),
                      Kg + (size_t)((kt + 1) * 64 + fr) * HS + fq + i * 8);
        }
        {
            const int vsn = p ? HVS1 : HVS0;
            #pragma unroll
            for (int i = 0; i < 2; i++)
                cpa16(sm2u(&smh[vsn + fr * KST16 + fq + i * 8]),
                      Vg + (size_t)fr * SEQ + kt * 64 + fq + i * 8);
        }
        cpa_commit();

        if (wid < 4) {
            const int kso = p ? HKS1 : HKS0;
            float S[8][4];
            #pragma unroll
            for (int nb = 0; nb < 8; nb++)
                #pragma unroll
                for (int j = 0; j < 4; j++) S[nb][j] = 0.f;
            #pragma unroll
            for (int kg = 0; kg < 4; kg++) {
                #pragma unroll
                for (int nb = 0; nb < 8; nb++) {
                    u64 bb = *(const u64*)
                        &smh[kso + (nb * 8 + grp) * KST16 + kg * 16 + 4 * t4];
                    mma16(S[nb], aq[kg][0], aq[kg][1], aq[kg][2], aq[kg][3],
                          lo32(bb), hi32(bb));
                }
            }
            if (kt == qt) {
                #pragma unroll
                for (int nb = 0; nb < 8; nb++) {
                    int c0 = nb * 8 + 2 * t4;
                    if (c0     > r0)     S[nb][0] = -1e30f;
                    if (c0 + 1 > r0)     S[nb][1] = -1e30f;
                    if (c0     > r0 + 8) S[nb][2] = -1e30f;
                    if (c0 + 1 > r0 + 8) S[nb][3] = -1e30f;
                }
            }
            const int pso = p ? HPS1 : HPS0;
            #pragma unroll
            for (int nb = 0; nb < 8; nb++) {
                float p0 = __expf(S[nb][0]);
                float p1 = __expf(S[nb][1]);
                float p2 = __expf(S[nb][2]);
                float p3 = __expf(S[nb][3]);
                l0 += p0 + p1;
                l1 += p2 + p3;
                const int pp = ((nb >> 1) << 4) + 4 * t4 + ((nb & 1) << 1);
                *(u32*)&smh[pso + r0 * KST16 + pp] =
                    h2u(__floats2half2_rn(p0, p1));
                *(u32*)&smh[pso + (r0 + 8) * KST16 + pp] =
                    h2u(__floats2half2_rn(p2, p3));
            }
        } else if (kt > 0) {
            const int q2 = p ^ 1;
            const int pso = q2 ? HPS1 : HPS0;
            const int vso = q2 ? HVS1 : HVS0;
            #pragma unroll
            for (int kg = 0; kg < 4; kg++) {
                u64 pa = *(const u64*)&smh[pso + r0 * KST16 + kg * 16 + 4 * t4];
                u64 pb = *(const u64*)&smh[pso + (r0 + 8) * KST16 + kg * 16 + 4 * t4];
                #pragma unroll
                for (int nb = 0; nb < 8; nb++) {
                    u64 vv = *(const u64*)
                        &smh[vso + (nb * 8 + grp) * KST16 + kg * 16 + 4 * t4];
                    mma16(acc[nb], lo32(pa), lo32(pb), hi32(pa), hi32(pb),
                          lo32(vv), hi32(vv));
                }
            }
        }
    }

    cpa_wait<0>();
    __syncthreads();
    if (wid < 4) {
        l0 += __shfl_xor_sync(0xffffffffu, l0, 1);
        l0 += __shfl_xor_sync(0xffffffffu, l0, 2);
        l1 += __shfl_xor_sync(0xffffffffu, l1, 1);
        l1 += __shfl_xor_sync(0xffffffffu, l1, 2);
        if (t4 == 0) {
            ALSf[r0]     = l0;
            ALSf[r0 + 8] = l1;
        }
    } else {
        const int q2 = qt & 1;
        const int pso = q2 ? HPS1 : HPS0;
        const int vso = q2 ? HVS1 : HVS0;
        #pragma unroll
        for (int kg = 0; kg < 4; kg++) {
            u64 pa = *(const u64*)&smh[pso + r0 * KST16 + kg * 16 + 4 * t4];
            u64 pb = *(const u64*)&smh[pso + (r0 + 8) * KST16 + kg * 16 + 4 * t4];
            #pragma unroll
            for (int nb = 0; nb < 8; nb++) {
                u64 vv = *(const u64*)
                    &smh[vso + (nb * 8 + grp) * KST16 + kg * 16 + 4 * t4];
                mma16(acc[nb], lo32(pa), lo32(pb), hi32(pa), hi32(pb),
                      lo32(vv), hi32(vv));
            }
        }
    }
    __syncthreads();
    if (wid >= 4) {
        const float inv0 = 1.0f / ALSf[r0];
        const float inv1 = 1.0f / ALSf[r0 + 8];
        float* o0 = out + ((size_t)b * SEQ + qrow0 + r0) * HS;
        float* o8 = o0 + 8 * HS;
        #pragma unroll
        for (int nb = 0; nb < 8; nb++) {
            *(u64*)(o0 + nb * 8 + 2 * t4) =
                pack2(acc[nb][0] * inv0, acc[nb][1] * inv0);
            *(u64*)(o8 + nb * 8 + 2 * t4) =
                pack2(acc[nb][2] * inv1, acc[nb][3] * inv1);
        }
    }
}

extern "C" void kernel_launch(void* const* d_in, const int* in_sizes, int n_in,
                              void* d_out, int out_size)
{
    (void)in_sizes; (void)n_in; (void)out_size;
    const float* index  = (const float*)d_in[0];
    const float* memory = (const float*)d_in[1];
    const float* Wq     = (const float*)d_in[2];
    const float* Wk     = (const float*)d_in[3];
    const float* Wv     = (const float*)d_in[4];
    float* out = (float*)d_out;

    cudaFuncSetAttribute(proj_kernel,
                         cudaFuncAttributeMaxDynamicSharedMemorySize, PROJ_SMB);
    cudaFuncSetAttribute(attn_kernel,
                         cudaFuncAttributeMaxDynamicSharedMemorySize, ASMB);

    prep_w<<<64, 256>>>(Wq, Wk, Wv);
    proj_kernel<<<dim3(128, 2), 256, PROJ_SMB>>>(index, memory);
    attn_kernel<<<dim3(32, 8), 256, ASMB>>>(out);
}